// round 1
// baseline (speedup 1.0000x reference)
#include <cuda_runtime.h>
#include <math.h>

#define TT 512
#define BB 16
#define HH 48
#define SS 4
#define OO 48
#define DD 768
#define NN 9216      /* S*H*O */
#define MTOT 8192    /* B*T */
#define MC 1024      /* GEMM chunk rows */
#define NCHUNK 8

// ---------------- device scratch ----------------
__device__ float g_logits[MC * NN];          // 36 MB chunk buffer
__device__ float g_lep[MTOT * HH];
__device__ float g_elep[MTOT * HH];
__device__ float g_log_alpha[MTOT * HH];
__device__ float g_log_beta[MTOT * HH];
__device__ float g_partial[MTOT];
__device__ float g_lp[HH];
__device__ float g_log_trans[HH * HH];
__device__ float g_trans_prob[HH * HH];
__device__ float g_emiss_prob[SS * HH * OO];

// ---------------- fast exp (FMA pipe only) ----------------
__device__ __forceinline__ float fexp(float x) {
    if (x < -87.0f) return 0.0f;
    float t = x * 1.4426950408889634f;
    float n = rintf(t);
    float f = t - n;
    float p = 1.5403530393381609e-4f;
    p = fmaf(p, f, 1.3333558146428443e-3f);
    p = fmaf(p, f, 9.6181291076284772e-3f);
    p = fmaf(p, f, 5.5504108664821580e-2f);
    p = fmaf(p, f, 2.4022650695910072e-1f);
    p = fmaf(p, f, 6.9314718055994531e-1f);
    p = fmaf(p, f, 1.0f);
    int e = (int)n;
    if (e < -126) return 0.0f;
    if (e > 126) e = 126;
    return p * __int_as_float((e + 127) << 23);
}

// ---------------- block reductions (256 threads) ----------------
__device__ __forceinline__ float blockSum256(float v, float* red) {
    int tid = threadIdx.x;
#pragma unroll
    for (int o = 16; o > 0; o >>= 1) v += __shfl_down_sync(0xffffffffu, v, o);
    __syncthreads();
    if ((tid & 31) == 0) red[tid >> 5] = v;
    __syncthreads();
    if (tid < 32) {
        float r = (tid < 8) ? red[tid] : 0.0f;
#pragma unroll
        for (int o = 4; o > 0; o >>= 1) r += __shfl_down_sync(0xffffffffu, r, o);
        if (tid == 0) red[0] = r;
    }
    __syncthreads();
    return red[0];
}

__device__ __forceinline__ float blockMax256(float v, float* red) {
    int tid = threadIdx.x;
#pragma unroll
    for (int o = 16; o > 0; o >>= 1) v = fmaxf(v, __shfl_down_sync(0xffffffffu, v, o));
    __syncthreads();
    if ((tid & 31) == 0) red[tid >> 5] = v;
    __syncthreads();
    if (tid < 32) {
        float r = (tid < 8) ? red[tid] : -3.0e38f;
#pragma unroll
        for (int o = 4; o > 0; o >>= 1) r = fmaxf(r, __shfl_down_sync(0xffffffffu, r, o));
        if (tid == 0) red[0] = r;
    }
    __syncthreads();
    return red[0];
}

// ---------------- kernel 0: small preprocessing ----------------
__global__ void prep_kernel(const float* __restrict__ sp,
                            const float* __restrict__ ut,
                            const float* __restrict__ ue) {
    int tid = threadIdx.x;
    if (tid < HH) {  // log_softmax rows of trans
        const float* row = ut + tid * HH;
        float m = row[0];
#pragma unroll
        for (int j = 1; j < HH; j++) m = fmaxf(m, row[j]);
        float s = 0.0f;
#pragma unroll
        for (int j = 0; j < HH; j++) s += fexp(row[j] - m);
        float ls = logf(s) + m;
#pragma unroll
        for (int j = 0; j < HH; j++) {
            float v = row[j] - ls;
            g_log_trans[tid * HH + j] = v;
            g_trans_prob[tid * HH + j] = fexp(v);
        }
    }
    if (tid < SS * HH) {  // softmax rows of emiss
        const float* row = ue + tid * OO;
        float m = row[0];
#pragma unroll
        for (int j = 1; j < OO; j++) m = fmaxf(m, row[j]);
        float s = 0.0f;
#pragma unroll
        for (int j = 0; j < OO; j++) s += fexp(row[j] - m);
        float inv = 1.0f / s;
#pragma unroll
        for (int j = 0; j < OO; j++) g_emiss_prob[tid * OO + j] = fexp(row[j] - m) * inv;
    }
    if (tid == 0) {  // log_softmax of priors
        float m = sp[0];
        for (int j = 1; j < HH; j++) m = fmaxf(m, sp[j]);
        float s = 0.0f;
        for (int j = 0; j < HH; j++) s += fexp(sp[j] - m);
        float ls = logf(s) + m;
        for (int j = 0; j < HH; j++) g_lp[j] = sp[j] - ls;
    }
}

// ---------------- kernel 1: fp32 SGEMM logits chunk ----------------
// C[lm, n] = sum_k A[m0+lm, k] * W[n, k] + bias[n]
__global__ void __launch_bounds__(256) gemm_kernel(const float* __restrict__ A,
                                                   const float* __restrict__ W,
                                                   const float* __restrict__ bias,
                                                   int m0) {
    const int BM = 128, BN = 128, BK = 16;
    __shared__ float As[BK][BM];
    __shared__ float Bs[BK][BN];
    int tid = threadIdx.x;
    int bm = blockIdx.y * BM;
    int bn = blockIdx.x * BN;
    int tm = (tid >> 4) << 3;   // 0..120
    int tn = (tid & 15) << 3;   // 0..120
    int lrow = tid >> 2;        // 0..63
    int lkq = (tid & 3) << 2;   // 0,4,8,12

    float acc[8][8];
#pragma unroll
    for (int i = 0; i < 8; i++)
#pragma unroll
        for (int j = 0; j < 8; j++) acc[i][j] = 0.0f;

    for (int k0 = 0; k0 < DD; k0 += BK) {
#pragma unroll
        for (int r = 0; r < 2; r++) {
            int row = lrow + r * 64;
            float4 v = *(const float4*)&A[(size_t)(m0 + bm + row) * DD + k0 + lkq];
            As[lkq + 0][row] = v.x; As[lkq + 1][row] = v.y;
            As[lkq + 2][row] = v.z; As[lkq + 3][row] = v.w;
            float4 u = *(const float4*)&W[(size_t)(bn + row) * DD + k0 + lkq];
            Bs[lkq + 0][row] = u.x; Bs[lkq + 1][row] = u.y;
            Bs[lkq + 2][row] = u.z; Bs[lkq + 3][row] = u.w;
        }
        __syncthreads();
#pragma unroll
        for (int k = 0; k < BK; k++) {
            float4 a0 = *(const float4*)&As[k][tm];
            float4 a1 = *(const float4*)&As[k][tm + 4];
            float4 b0 = *(const float4*)&Bs[k][tn];
            float4 b1 = *(const float4*)&Bs[k][tn + 4];
            float a[8] = {a0.x, a0.y, a0.z, a0.w, a1.x, a1.y, a1.z, a1.w};
            float bb[8] = {b0.x, b0.y, b0.z, b0.w, b1.x, b1.y, b1.z, b1.w};
#pragma unroll
            for (int i = 0; i < 8; i++)
#pragma unroll
                for (int j = 0; j < 8; j++) acc[i][j] = fmaf(a[i], bb[j], acc[i][j]);
        }
        __syncthreads();
    }
    float breg[8];
#pragma unroll
    for (int j = 0; j < 8; j++) breg[j] = bias[bn + tn + j];
#pragma unroll
    for (int i = 0; i < 8; i++) {
        size_t base = (size_t)(bm + tm + i) * NN + bn + tn;
        float4 o0, o1;
        o0.x = acc[i][0] + breg[0]; o0.y = acc[i][1] + breg[1];
        o0.z = acc[i][2] + breg[2]; o0.w = acc[i][3] + breg[3];
        o1.x = acc[i][4] + breg[4]; o1.y = acc[i][5] + breg[5];
        o1.z = acc[i][6] + breg[6]; o1.w = acc[i][7] + breg[7];
        *(float4*)&g_logits[base] = o0;
        *(float4*)&g_logits[base + 4] = o1;
    }
}

// ---------------- kernel 2: softmax + mixture -> lep/elep ----------------
// one block per (b,t) row of this chunk; 192 threads = (s,h) rows
__global__ void __launch_bounds__(192) lep_kernel(const float* __restrict__ obs, int m0) {
    __shared__ float sl[192 * 49];   // padded rows (48 + 1)
    __shared__ float sobs[192];
    __shared__ float sval[192];
    int tid = threadIdx.x;
    int lbt = blockIdx.x;
    int bt = m0 + lbt;

    const float4* src = (const float4*)(g_logits + (size_t)lbt * NN);
    for (int i = tid; i < NN / 4; i += 192) {
        float4 v = src[i];
        int n = i * 4;
        int r = n / OO;
        int o = n - r * OO;
        float* d = &sl[r * 49 + o];
        d[0] = v.x; d[1] = v.y; d[2] = v.z; d[3] = v.w;
    }
    sobs[tid] = obs[(size_t)bt * (SS * OO) + tid];
    __syncthreads();

    int s = tid / HH;
    const float* row = &sl[tid * 49];
    const float* ob = &sobs[s * OO];
    float m = row[0];
#pragma unroll
    for (int o = 1; o < OO; o++) m = fmaxf(m, row[o]);
    float den = 0.0f, dot = 0.0f;
#pragma unroll
    for (int o = 0; o < OO; o++) {
        float e = fexp(row[o] - m);
        den += e;
        dot = fmaf(e, ob[o], dot);
    }
    float eobs = 0.0f;
    const float* ep = &g_emiss_prob[tid * OO];
#pragma unroll
    for (int o = 0; o < OO; o++) eobs = fmaf(ep[o], ob[o], eobs);
    sval[tid] = 0.5f * eobs + 0.5f * (dot / den);
    __syncthreads();

    if (tid < HH) {
        float p = sval[tid] * sval[HH + tid] * sval[2 * HH + tid] * sval[3 * HH + tid];
        g_elep[(size_t)bt * HH + tid] = p;
        g_lep[(size_t)bt * HH + tid] = logf(p);
    }
}

// ---------------- kernel 3: forward+backward scans ----------------
// blocks 0..15 = forward (per b), 16..31 = backward. 64 threads.
__global__ void __launch_bounds__(64) scan_kernel() {
    __shared__ float tp[HH * HH];
    __shared__ float vec[HH];
    __shared__ float wbuf[HH];
    __shared__ float ubuf[HH];
    __shared__ float ssum;
    int tid = threadIdx.x;
    int b = blockIdx.x & 15;
    bool fwd = blockIdx.x < 16;

    if (fwd) {
        for (int i = tid; i < HH * HH; i += 64) tp[i] = g_trans_prob[i];
        if (tid < HH) wbuf[tid] = fexp(g_lp[tid]) * g_elep[(size_t)(b * TT) * HH + tid];
        __syncthreads();
        if (tid < 32) {
            float r = wbuf[tid] + ((tid < 16) ? wbuf[tid + 32] : 0.0f);
#pragma unroll
            for (int o = 16; o > 0; o >>= 1) r += __shfl_down_sync(0xffffffffu, r, o);
            if (tid == 0) ssum = r;
        }
        __syncthreads();
        if (tid < HH) {
            float a = wbuf[tid] / ssum;
            vec[tid] = a;
            g_log_alpha[(size_t)(b * TT) * HH + tid] = logf(a);
        }
        __syncthreads();
        for (int t = 1; t < TT; t++) {
            float el = (tid < HH) ? g_elep[(size_t)(b * TT + t) * HH + tid] : 0.0f;
            if (tid < HH) {
                float v0 = 0, v1 = 0, v2 = 0, v3 = 0;
#pragma unroll
                for (int i = 0; i < HH; i += 4) {
                    v0 = fmaf(vec[i + 0], tp[(i + 0) * HH + tid], v0);
                    v1 = fmaf(vec[i + 1], tp[(i + 1) * HH + tid], v1);
                    v2 = fmaf(vec[i + 2], tp[(i + 2) * HH + tid], v2);
                    v3 = fmaf(vec[i + 3], tp[(i + 3) * HH + tid], v3);
                }
                wbuf[tid] = (v0 + v1 + v2 + v3) * el;
            }
            __syncthreads();
            if (tid < 32) {
                float r = wbuf[tid] + ((tid < 16) ? wbuf[tid + 32] : 0.0f);
#pragma unroll
                for (int o = 16; o > 0; o >>= 1) r += __shfl_down_sync(0xffffffffu, r, o);
                if (tid == 0) ssum = r;
            }
            __syncthreads();
            if (tid < HH) {
                float a = wbuf[tid] / ssum;
                vec[tid] = a;
                g_log_alpha[(size_t)(b * TT + t) * HH + tid] = logf(a);
            }
            __syncthreads();
        }
    } else {
        // transposed trans for conflict-free access
        for (int idx = tid; idx < HH * HH; idx += 64) {
            int i = idx / HH, j = idx - i * HH;
            tp[j * HH + i] = g_trans_prob[idx];
        }
        if (tid < HH) {
            vec[tid] = 1.0f;
            g_log_beta[(size_t)(b * TT + TT - 1) * HH + tid] = 0.0f;
        }
        __syncthreads();
        for (int t = TT - 2; t >= 0; t--) {
            if (tid < HH) ubuf[tid] = g_elep[(size_t)(b * TT + t) * HH + tid] * vec[tid];
            __syncthreads();
            if (tid < HH) {
                float v0 = 0, v1 = 0, v2 = 0, v3 = 0;
#pragma unroll
                for (int j = 0; j < HH; j += 4) {
                    v0 = fmaf(tp[(j + 0) * HH + tid], ubuf[j + 0], v0);
                    v1 = fmaf(tp[(j + 1) * HH + tid], ubuf[j + 1], v1);
                    v2 = fmaf(tp[(j + 2) * HH + tid], ubuf[j + 2], v2);
                    v3 = fmaf(tp[(j + 3) * HH + tid], ubuf[j + 3], v3);
                }
                wbuf[tid] = v0 + v1 + v2 + v3;
            }
            __syncthreads();
            if (tid < 32) {
                float r = wbuf[tid] + ((tid < 16) ? wbuf[tid + 32] : 0.0f);
#pragma unroll
                for (int o = 16; o > 0; o >>= 1) r += __shfl_down_sync(0xffffffffu, r, o);
                if (tid == 0) ssum = r;
            }
            __syncthreads();
            if (tid < HH) {
                float bb = wbuf[tid] / ssum;
                vec[tid] = bb;
                g_log_beta[(size_t)(b * TT + t) * HH + tid] = logf(bb);
            }
            __syncthreads();
        }
    }
}

// ---------------- kernel 4: per-(b,t) gamma / prior / xi terms ----------------
__global__ void __launch_bounds__(256) final_kernel(const int* __restrict__ seq) {
    __shared__ float lt[HH * HH];
    __shared__ float sA[HH], sB[HH], sG[HH], sL[HH];
    __shared__ float red[32];
    int tid = threadIdx.x;
    int bt = blockIdx.x;
    int b = bt >> 9;
    int t = bt & (TT - 1);
    int len = seq[b];

    for (int i = tid; i < HH * HH; i += 256) lt[i] = g_log_trans[i];
    if (tid < HH) {
        int tb = (t + TT - len) & (TT - 1);  // rolled beta index
        float br = g_log_beta[(size_t)(b * TT + tb) * HH + tid];
        float at = g_log_alpha[(size_t)(b * TT + t) * HH + tid];
        float lpv = g_lep[(size_t)(b * TT + t) * HH + tid];
        sG[tid] = at + br;
        sB[tid] = lpv + br;
        sL[tid] = lpv;
        sA[tid] = (t > 0) ? g_log_alpha[(size_t)(b * TT + t - 1) * HH + tid] : 0.0f;
    }
    __syncthreads();

    // gamma (lognorm over H) -> emis term and prior term
    float gv = (tid < HH) ? sG[tid] : -3.0e38f;
    float M1 = blockMax256(gv, red);
    float e = (tid < HH) ? fexp(sG[tid] - M1) : 0.0f;
    float Z = blockSum256(e, red);
    float E = blockSum256(e * ((tid < HH) ? sL[tid] : 0.0f), red);
    float total = 0.0f;
    if (t < len) total += E / Z;
    if (t == 0) {
        float P = blockSum256(e * ((tid < HH) ? g_lp[tid] : 0.0f), red);
        total += P / Z;
    }

    // xi term (joint normalization over H*H)
    if (t >= 1 && t < len) {
        float lm = -3.0e38f;
        for (int idx = tid; idx < HH * HH; idx += 256) {
            int i = idx / HH, j = idx - i * HH;
            lm = fmaxf(lm, lt[idx] + sA[i] + sB[j]);
        }
        float M2 = blockMax256(lm, red);
        float z = 0.0f, w = 0.0f;
        for (int idx = tid; idx < HH * HH; idx += 256) {
            int i = idx / HH, j = idx - i * HH;
            float ltv = lt[idx];
            float ex = fexp(ltv + sA[i] + sB[j] - M2);
            z += ex;
            w = fmaf(ex, ltv, w);
        }
        float Z2 = blockSum256(z, red);
        float W2 = blockSum256(w, red);
        total += W2 / Z2;
    }
    if (tid == 0) g_partial[bt] = total;
}

// ---------------- kernel 5: deterministic final reduction ----------------
__global__ void __launch_bounds__(256) reduce_kernel(float* __restrict__ out) {
    __shared__ float red[256];
    int tid = threadIdx.x;
    float s = 0.0f;
    for (int i = tid; i < MTOT; i += 256) s += g_partial[i];
    red[tid] = s;
    __syncthreads();
    for (int off = 128; off > 0; off >>= 1) {
        if (tid < off) red[tid] += red[tid + off];
        __syncthreads();
    }
    if (tid == 0) out[0] = red[0] * (1.0f / (float)BB);
}

// ---------------- launch ----------------
extern "C" void kernel_launch(void* const* d_in, const int* in_sizes, int n_in,
                              void* d_out, int out_size) {
    const float* emb   = (const float*)d_in[0];
    const float* obs   = (const float*)d_in[1];
    const float* sp    = (const float*)d_in[2];
    const float* ut    = (const float*)d_in[3];
    const float* ue    = (const float*)d_in[4];
    const float* Wm    = (const float*)d_in[5];
    const float* bias  = (const float*)d_in[6];
    const int*   seq   = (const int*)d_in[7];
    float* out = (float*)d_out;

    prep_kernel<<<1, 192>>>(sp, ut, ue);

    dim3 ggrid(NN / 128, MC / 128);
    for (int c = 0; c < NCHUNK; c++) {
        int m0 = c * MC;
        gemm_kernel<<<ggrid, 256>>>(emb, Wm, bias, m0);
        lep_kernel<<<MC, 192>>>(obs, m0);
    }

    scan_kernel<<<32, 64>>>();
    final_kernel<<<MTOT, 256>>>(seq);
    reduce_kernel<<<1, 256>>>(out);
}

// round 3
// speedup vs baseline: 3.2364x; 3.2364x over previous
#include <cuda_runtime.h>
#include <cuda_bf16.h>
#include <math.h>
#include <stdint.h>

#define TT 512
#define BB 16
#define HH 48
#define SS 4
#define OO 48
#define DD 768
#define NN 9216      /* S*H*O */
#define MTOT 8192    /* B*T */
#define MC 1024      /* GEMM chunk rows */
#define NCHUNK 8

// ---------------- device scratch ----------------
__device__ float g_logits[MC * NN];          // 36 MB chunk buffer
__device__ __nv_bfloat16 g_emb16[MTOT * DD]; // 12.6 MB
__device__ __nv_bfloat16 g_w16[NN * DD];     // 14.2 MB
__device__ float g_lep[MTOT * HH];
__device__ float g_elep[MTOT * HH];
__device__ float g_log_alpha[MTOT * HH];
__device__ float g_log_beta[MTOT * HH];
__device__ float g_partial[MTOT];
__device__ float g_lp[HH];
__device__ float g_log_trans[HH * HH];
__device__ float g_trans_prob[HH * HH];
__device__ float g_emiss_prob[SS * HH * OO];

// ---------------- helpers ----------------
__device__ __forceinline__ uint32_t smem_u32(const void* p) {
    uint32_t a;
    asm("{ .reg .u64 t; cvta.to.shared.u64 t, %1; cvt.u32.u64 %0, t; }" : "=r"(a) : "l"(p));
    return a;
}

__device__ __forceinline__ float fexp(float x) {
    if (x < -87.0f) return 0.0f;
    float t = x * 1.4426950408889634f;
    float n = rintf(t);
    float f = t - n;
    float p = 1.5403530393381609e-4f;
    p = fmaf(p, f, 1.3333558146428443e-3f);
    p = fmaf(p, f, 9.6181291076284772e-3f);
    p = fmaf(p, f, 5.5504108664821580e-2f);
    p = fmaf(p, f, 2.4022650695910072e-1f);
    p = fmaf(p, f, 6.9314718055994531e-1f);
    p = fmaf(p, f, 1.0f);
    int e = (int)n;
    if (e < -126) return 0.0f;
    if (e > 126) e = 126;
    return p * __int_as_float((e + 127) << 23);
}

__device__ __forceinline__ float blockSum256(float v, float* red) {
    int tid = threadIdx.x;
#pragma unroll
    for (int o = 16; o > 0; o >>= 1) v += __shfl_down_sync(0xffffffffu, v, o);
    __syncthreads();
    if ((tid & 31) == 0) red[tid >> 5] = v;
    __syncthreads();
    if (tid < 32) {
        float r = (tid < 8) ? red[tid] : 0.0f;
#pragma unroll
        for (int o = 4; o > 0; o >>= 1) r += __shfl_down_sync(0xffffffffu, r, o);
        if (tid == 0) red[0] = r;
    }
    __syncthreads();
    return red[0];
}

__device__ __forceinline__ float blockMax256(float v, float* red) {
    int tid = threadIdx.x;
#pragma unroll
    for (int o = 16; o > 0; o >>= 1) v = fmaxf(v, __shfl_down_sync(0xffffffffu, v, o));
    __syncthreads();
    if ((tid & 31) == 0) red[tid >> 5] = v;
    __syncthreads();
    if (tid < 32) {
        float r = (tid < 8) ? red[tid] : -3.0e38f;
#pragma unroll
        for (int o = 4; o > 0; o >>= 1) r = fmaxf(r, __shfl_down_sync(0xffffffffu, r, o));
        if (tid == 0) red[0] = r;
    }
    __syncthreads();
    return red[0];
}

// ---------------- kernel 0: small preprocessing ----------------
__global__ void prep_kernel(const float* __restrict__ sp,
                            const float* __restrict__ ut,
                            const float* __restrict__ ue) {
    int tid = threadIdx.x;
    if (tid < HH) {
        const float* row = ut + tid * HH;
        float m = row[0];
#pragma unroll
        for (int j = 1; j < HH; j++) m = fmaxf(m, row[j]);
        float s = 0.0f;
#pragma unroll
        for (int j = 0; j < HH; j++) s += fexp(row[j] - m);
        float ls = logf(s) + m;
#pragma unroll
        for (int j = 0; j < HH; j++) {
            float v = row[j] - ls;
            g_log_trans[tid * HH + j] = v;
            g_trans_prob[tid * HH + j] = fexp(v);
        }
    }
    if (tid < SS * HH) {
        const float* row = ue + tid * OO;
        float m = row[0];
#pragma unroll
        for (int j = 1; j < OO; j++) m = fmaxf(m, row[j]);
        float s = 0.0f;
#pragma unroll
        for (int j = 0; j < OO; j++) s += fexp(row[j] - m);
        float inv = 1.0f / s;
#pragma unroll
        for (int j = 0; j < OO; j++) g_emiss_prob[tid * OO + j] = fexp(row[j] - m) * inv;
    }
    if (tid == 0) {
        float m = sp[0];
        for (int j = 1; j < HH; j++) m = fmaxf(m, sp[j]);
        float s = 0.0f;
        for (int j = 0; j < HH; j++) s += fexp(sp[j] - m);
        float ls = logf(s) + m;
        for (int j = 0; j < HH; j++) g_lp[j] = sp[j] - ls;
    }
}

// ---------------- kernel 0b: fp32 -> bf16 conversion ----------------
__global__ void __launch_bounds__(256) convert_kernel(const float* __restrict__ emb,
                                                      const float* __restrict__ Wm) {
    const int nA = MTOT * DD / 4;
    const int nW = NN * DD / 4;
    int i = blockIdx.x * 256 + threadIdx.x;
    if (i < nA) {
        float4 v = ((const float4*)emb)[i];
        __nv_bfloat162 lo = __floats2bfloat162_rn(v.x, v.y);
        __nv_bfloat162 hi = __floats2bfloat162_rn(v.z, v.w);
        ((__nv_bfloat162*)g_emb16)[i * 2] = lo;
        ((__nv_bfloat162*)g_emb16)[i * 2 + 1] = hi;
    } else if (i < nA + nW) {
        int j = i - nA;
        float4 v = ((const float4*)Wm)[j];
        __nv_bfloat162 lo = __floats2bfloat162_rn(v.x, v.y);
        __nv_bfloat162 hi = __floats2bfloat162_rn(v.z, v.w);
        ((__nv_bfloat162*)g_w16)[j * 2] = lo;
        ((__nv_bfloat162*)g_w16)[j * 2 + 1] = hi;
    }
}

// ---------------- kernel 1: bf16 mma.sync GEMM (128x128x64 tiles) ----------------
// logits[bm+m, bn+n] = sum_d emb16[m0+bm+m, d] * w16[bn+n, d] + bias[bn+n]
#define GEMM_SMEM 65536
__device__ __forceinline__ void cp_async16(uint32_t dst, const void* src) {
    asm volatile("cp.async.cg.shared.global [%0], [%1], 16;" ::
                 "r"(dst), "l"(__cvta_generic_to_global(src)));
}

__global__ void __launch_bounds__(256) mma_gemm_kernel(const float* __restrict__ bias, int m0) {
    extern __shared__ char smem[];
    uint32_t sbase = smem_u32(smem);
    const int tid = threadIdx.x;
    const int wid = tid >> 5, lane = tid & 31;
    const int bn = blockIdx.x * 128;
    const int bm_g = m0 + blockIdx.y * 128;   // global A row base
    const int wm = (wid & 1) * 64;            // warp M offset (0/64)
    const int wn = (wid >> 1) * 32;           // warp N offset (0..96)

    // smem: A buf0 @0, A buf1 @16384, B buf0 @32768, B buf1 @49152
    // each tile: 128 rows x 64 bf16 (128 B/row), SW128-style XOR swizzle

    // ---- fragment address precompute ----
    const int sub = lane >> 3, l8 = lane & 7;
    // A ldmatrix.x4 mapping: sub0: rows0-7 k0 | sub1: rows8-15 k0 | sub2: rows0-7 k+16B | sub3: rows8-15 k+16B
    const int a_row_in = (sub & 1) * 8 + l8;
    const int a_kb = (sub >> 1) * 16;
    // B ldmatrix.x4 mapping (two n8 frags): sub0: n0-7 k0 | sub1: n0-7 k16 | sub2: n8-15 k0 | sub3: n8-15 k16
    const int b_row_in = (sub >> 1) * 8 + l8;
    const int b_kb = (sub & 1) * 16;

    uint32_t a_base[4], b_base[2];
    int a_xor[4], b_xor[2];
#pragma unroll
    for (int mi = 0; mi < 4; mi++) {
        int r = wm + mi * 16 + a_row_in;
        a_base[mi] = (uint32_t)(r * 128);
        a_xor[mi] = (r & 7) << 4;
    }
#pragma unroll
    for (int pi = 0; pi < 2; pi++) {
        int r = wn + pi * 16 + b_row_in;
        b_base[pi] = (uint32_t)(r * 128);
        b_xor[pi] = (r & 7) << 4;
    }

    float c[4][4][4];
#pragma unroll
    for (int mi = 0; mi < 4; mi++)
#pragma unroll
        for (int ni = 0; ni < 4; ni++)
#pragma unroll
            for (int q = 0; q < 4; q++) c[mi][ni][q] = 0.0f;

    // ---- tile loader ----
    auto load_tiles = [&](int kb, int buf) {
        uint32_t adst = sbase + (uint32_t)(buf * 16384);
        uint32_t bdst = sbase + 32768u + (uint32_t)(buf * 16384);
#pragma unroll
        for (int p = 0; p < 4; p++) {
            int idx = tid + p * 256;
            int r = idx >> 3, cc = idx & 7;
            uint32_t off = (uint32_t)(r * 128 + cc * 16);
            off ^= (uint32_t)((r & 7) << 4);
            cp_async16(adst + off, g_emb16 + (size_t)(bm_g + r) * DD + kb * 64 + cc * 8);
            cp_async16(bdst + off, g_w16 + (size_t)(bn + r) * DD + kb * 64 + cc * 8);
        }
        asm volatile("cp.async.commit_group;" ::: "memory");
    };

    load_tiles(0, 0);
    load_tiles(1, 1);

    for (int kb = 0; kb < 12; kb++) {
        int buf = kb & 1;
        if (kb < 11) asm volatile("cp.async.wait_group 1;" ::: "memory");
        else         asm volatile("cp.async.wait_group 0;" ::: "memory");
        __syncthreads();

        uint32_t abuf = sbase + (uint32_t)(buf * 16384);
        uint32_t bbuf = sbase + 32768u + (uint32_t)(buf * 16384);
#pragma unroll
        for (int ks = 0; ks < 4; ks++) {
            uint32_t a[4][4];
#pragma unroll
            for (int mi = 0; mi < 4; mi++) {
                uint32_t addr = abuf + a_base[mi] + (uint32_t)((ks * 32 + a_kb) ^ a_xor[mi]);
                asm volatile("ldmatrix.sync.aligned.m8n8.x4.shared.b16 {%0,%1,%2,%3}, [%4];"
                             : "=r"(a[mi][0]), "=r"(a[mi][1]), "=r"(a[mi][2]), "=r"(a[mi][3])
                             : "r"(addr));
            }
            uint32_t b[4][2];
#pragma unroll
            for (int pi = 0; pi < 2; pi++) {
                uint32_t addr = bbuf + b_base[pi] + (uint32_t)((ks * 32 + b_kb) ^ b_xor[pi]);
                uint32_t r0, r1, r2, r3;
                asm volatile("ldmatrix.sync.aligned.m8n8.x4.shared.b16 {%0,%1,%2,%3}, [%4];"
                             : "=r"(r0), "=r"(r1), "=r"(r2), "=r"(r3) : "r"(addr));
                b[pi * 2][0] = r0; b[pi * 2][1] = r1;
                b[pi * 2 + 1][0] = r2; b[pi * 2 + 1][1] = r3;
            }
#pragma unroll
            for (int mi = 0; mi < 4; mi++)
#pragma unroll
                for (int ni = 0; ni < 4; ni++) {
                    asm volatile(
                        "mma.sync.aligned.m16n8k16.row.col.f32.bf16.bf16.f32 "
                        "{%0,%1,%2,%3}, {%4,%5,%6,%7}, {%8,%9}, {%0,%1,%2,%3};"
                        : "+f"(c[mi][ni][0]), "+f"(c[mi][ni][1]),
                          "+f"(c[mi][ni][2]), "+f"(c[mi][ni][3])
                        : "r"(a[mi][0]), "r"(a[mi][1]), "r"(a[mi][2]), "r"(a[mi][3]),
                          "r"(b[ni][0]), "r"(b[ni][1]));
                }
        }
        __syncthreads();
        if (kb + 2 < 12) load_tiles(kb + 2, buf);
    }

    // ---- epilogue: bias add + store ----
    const int trow = lane >> 2;          // 0..7
    const int tcol = (lane & 3) * 2;     // 0,2,4,6
    const int lrow_base = blockIdx.y * 128 + wm;
#pragma unroll
    for (int ni = 0; ni < 4; ni++) {
        int cc = bn + wn + ni * 8 + tcol;
        float bx = __ldg(&bias[cc]);
        float by = __ldg(&bias[cc + 1]);
#pragma unroll
        for (int mi = 0; mi < 4; mi++) {
            int r0 = lrow_base + mi * 16 + trow;
            float2 v0 = {c[mi][ni][0] + bx, c[mi][ni][1] + by};
            float2 v1 = {c[mi][ni][2] + bx, c[mi][ni][3] + by};
            *(float2*)&g_logits[(size_t)r0 * NN + cc] = v0;
            *(float2*)&g_logits[(size_t)(r0 + 8) * NN + cc] = v1;
        }
    }
}

// ---------------- kernel 2: softmax + mixture -> lep/elep ----------------
__global__ void __launch_bounds__(192) lep_kernel(const float* __restrict__ obs, int m0) {
    __shared__ float sl[192 * 49];
    __shared__ float sobs[192];
    __shared__ float sval[192];
    int tid = threadIdx.x;
    int lbt = blockIdx.x;
    int bt = m0 + lbt;

    const float4* src = (const float4*)(g_logits + (size_t)lbt * NN);
    for (int i = tid; i < NN / 4; i += 192) {
        float4 v = src[i];
        int n = i * 4;
        int r = n / OO;
        int o = n - r * OO;
        float* d = &sl[r * 49 + o];
        d[0] = v.x; d[1] = v.y; d[2] = v.z; d[3] = v.w;
    }
    sobs[tid] = obs[(size_t)bt * (SS * OO) + tid];
    __syncthreads();

    int s = tid / HH;
    const float* row = &sl[tid * 49];
    const float* ob = &sobs[s * OO];
    float m = row[0];
#pragma unroll
    for (int o = 1; o < OO; o++) m = fmaxf(m, row[o]);
    float den = 0.0f, dot = 0.0f;
#pragma unroll
    for (int o = 0; o < OO; o++) {
        float e = fexp(row[o] - m);
        den += e;
        dot = fmaf(e, ob[o], dot);
    }
    float eobs = 0.0f;
    const float* ep = &g_emiss_prob[tid * OO];
#pragma unroll
    for (int o = 0; o < OO; o++) eobs = fmaf(ep[o], ob[o], eobs);
    sval[tid] = 0.5f * eobs + 0.5f * (dot / den);
    __syncthreads();

    if (tid < HH) {
        float p = sval[tid] * sval[HH + tid] * sval[2 * HH + tid] * sval[3 * HH + tid];
        g_elep[(size_t)bt * HH + tid] = p;
        g_lep[(size_t)bt * HH + tid] = logf(p);
    }
}

// ---------------- kernel 3: forward+backward scans ----------------
__global__ void __launch_bounds__(64) scan_kernel() {
    __shared__ float tp[HH * HH];
    __shared__ float vec[HH];
    __shared__ float wbuf[HH];
    __shared__ float ubuf[HH];
    __shared__ float ssum;
    int tid = threadIdx.x;
    int b = blockIdx.x & 15;
    bool fwd = blockIdx.x < 16;

    if (fwd) {
        for (int i = tid; i < HH * HH; i += 64) tp[i] = g_trans_prob[i];
        if (tid < HH) wbuf[tid] = fexp(g_lp[tid]) * g_elep[(size_t)(b * TT) * HH + tid];
        __syncthreads();
        if (tid < 32) {
            float r = wbuf[tid] + ((tid < 16) ? wbuf[tid + 32] : 0.0f);
#pragma unroll
            for (int o = 16; o > 0; o >>= 1) r += __shfl_down_sync(0xffffffffu, r, o);
            if (tid == 0) ssum = r;
        }
        __syncthreads();
        if (tid < HH) {
            float a = wbuf[tid] / ssum;
            vec[tid] = a;
            g_log_alpha[(size_t)(b * TT) * HH + tid] = logf(a);
        }
        __syncthreads();
        for (int t = 1; t < TT; t++) {
            float el = (tid < HH) ? g_elep[(size_t)(b * TT + t) * HH + tid] : 0.0f;
            if (tid < HH) {
                float v0 = 0, v1 = 0, v2 = 0, v3 = 0;
#pragma unroll
                for (int i = 0; i < HH; i += 4) {
                    v0 = fmaf(vec[i + 0], tp[(i + 0) * HH + tid], v0);
                    v1 = fmaf(vec[i + 1], tp[(i + 1) * HH + tid], v1);
                    v2 = fmaf(vec[i + 2], tp[(i + 2) * HH + tid], v2);
                    v3 = fmaf(vec[i + 3], tp[(i + 3) * HH + tid], v3);
                }
                wbuf[tid] = (v0 + v1 + v2 + v3) * el;
            }
            __syncthreads();
            if (tid < 32) {
                float r = wbuf[tid] + ((tid < 16) ? wbuf[tid + 32] : 0.0f);
#pragma unroll
                for (int o = 16; o > 0; o >>= 1) r += __shfl_down_sync(0xffffffffu, r, o);
                if (tid == 0) ssum = r;
            }
            __syncthreads();
            if (tid < HH) {
                float a = wbuf[tid] / ssum;
                vec[tid] = a;
                g_log_alpha[(size_t)(b * TT + t) * HH + tid] = logf(a);
            }
            __syncthreads();
        }
    } else {
        for (int idx = tid; idx < HH * HH; idx += 64) {
            int i = idx / HH, j = idx - i * HH;
            tp[j * HH + i] = g_trans_prob[idx];
        }
        if (tid < HH) {
            vec[tid] = 1.0f;
            g_log_beta[(size_t)(b * TT + TT - 1) * HH + tid] = 0.0f;
        }
        __syncthreads();
        for (int t = TT - 2; t >= 0; t--) {
            if (tid < HH) ubuf[tid] = g_elep[(size_t)(b * TT + t) * HH + tid] * vec[tid];
            __syncthreads();
            if (tid < HH) {
                float v0 = 0, v1 = 0, v2 = 0, v3 = 0;
#pragma unroll
                for (int j = 0; j < HH; j += 4) {
                    v0 = fmaf(tp[(j + 0) * HH + tid], ubuf[j + 0], v0);
                    v1 = fmaf(tp[(j + 1) * HH + tid], ubuf[j + 1], v1);
                    v2 = fmaf(tp[(j + 2) * HH + tid], ubuf[j + 2], v2);
                    v3 = fmaf(tp[(j + 3) * HH + tid], ubuf[j + 3], v3);
                }
                wbuf[tid] = v0 + v1 + v2 + v3;
            }
            __syncthreads();
            if (tid < 32) {
                float r = wbuf[tid] + ((tid < 16) ? wbuf[tid + 32] : 0.0f);
#pragma unroll
                for (int o = 16; o > 0; o >>= 1) r += __shfl_down_sync(0xffffffffu, r, o);
                if (tid == 0) ssum = r;
            }
            __syncthreads();
            if (tid < HH) {
                float bb = wbuf[tid] / ssum;
                vec[tid] = bb;
                g_log_beta[(size_t)(b * TT + t) * HH + tid] = logf(bb);
            }
            __syncthreads();
        }
    }
}

// ---------------- kernel 4: per-(b,t) gamma / prior / xi terms ----------------
__global__ void __launch_bounds__(256) final_kernel(const int* __restrict__ seq) {
    __shared__ float lt[HH * HH];
    __shared__ float sA[HH], sB[HH], sG[HH], sL[HH];
    __shared__ float red[32];
    int tid = threadIdx.x;
    int bt = blockIdx.x;
    int b = bt >> 9;
    int t = bt & (TT - 1);
    int len = seq[b];

    for (int i = tid; i < HH * HH; i += 256) lt[i] = g_log_trans[i];
    if (tid < HH) {
        int tb = (t + TT - len) & (TT - 1);
        float br = g_log_beta[(size_t)(b * TT + tb) * HH + tid];
        float at = g_log_alpha[(size_t)(b * TT + t) * HH + tid];
        float lpv = g_lep[(size_t)(b * TT + t) * HH + tid];
        sG[tid] = at + br;
        sB[tid] = lpv + br;
        sL[tid] = lpv;
        sA[tid] = (t > 0) ? g_log_alpha[(size_t)(b * TT + t - 1) * HH + tid] : 0.0f;
    }
    __syncthreads();

    float gv = (tid < HH) ? sG[tid] : -3.0e38f;
    float M1 = blockMax256(gv, red);
    float e = (tid < HH) ? fexp(sG[tid] - M1) : 0.0f;
    float Z = blockSum256(e, red);
    float E = blockSum256(e * ((tid < HH) ? sL[tid] : 0.0f), red);
    float total = 0.0f;
    if (t < len) total += E / Z;
    if (t == 0) {
        float P = blockSum256(e * ((tid < HH) ? g_lp[tid] : 0.0f), red);
        total += P / Z;
    }

    if (t >= 1 && t < len) {
        float lm = -3.0e38f;
        for (int idx = tid; idx < HH * HH; idx += 256) {
            int i = idx / HH, j = idx - i * HH;
            lm = fmaxf(lm, lt[idx] + sA[i] + sB[j]);
        }
        float M2 = blockMax256(lm, red);
        float z = 0.0f, w = 0.0f;
        for (int idx = tid; idx < HH * HH; idx += 256) {
            int i = idx / HH, j = idx - i * HH;
            float ltv = lt[idx];
            float ex = fexp(ltv + sA[i] + sB[j] - M2);
            z += ex;
            w = fmaf(ex, ltv, w);
        }
        float Z2 = blockSum256(z, red);
        float W2 = blockSum256(w, red);
        total += W2 / Z2;
    }
    if (tid == 0) g_partial[bt] = total;
}

// ---------------- kernel 5: deterministic final reduction ----------------
__global__ void __launch_bounds__(256) reduce_kernel(float* __restrict__ out) {
    __shared__ float red[256];
    int tid = threadIdx.x;
    float s = 0.0f;
    for (int i = tid; i < MTOT; i += 256) s += g_partial[i];
    red[tid] = s;
    __syncthreads();
    for (int off = 128; off > 0; off >>= 1) {
        if (tid < off) red[tid] += red[tid + off];
        __syncthreads();
    }
    if (tid == 0) out[0] = red[0] * (1.0f / (float)BB);
}

// ---------------- launch ----------------
extern "C" void kernel_launch(void* const* d_in, const int* in_sizes, int n_in,
                              void* d_out, int out_size) {
    const float* emb  = (const float*)d_in[0];
    const float* obs  = (const float*)d_in[1];
    const float* sp   = (const float*)d_in[2];
    const float* ut   = (const float*)d_in[3];
    const float* ue   = (const float*)d_in[4];
    const float* Wm   = (const float*)d_in[5];
    const float* bias = (const float*)d_in[6];
    const int*   seq  = (const int*)d_in[7];
    float* out = (float*)d_out;

    cudaFuncSetAttribute(mma_gemm_kernel, cudaFuncAttributeMaxDynamicSharedMemorySize, GEMM_SMEM);

    prep_kernel<<<1, 192>>>(sp, ut, ue);
    {
        const int nA = MTOT * DD / 4, nW = NN * DD / 4;
        convert_kernel<<<(nA + nW + 255) / 256, 256>>>(emb, Wm);
    }

    dim3 ggrid(NN / 128, MC / 128);
    for (int c = 0; c < NCHUNK; c++) {
        int m0 = c * MC;
        mma_gemm_kernel<<<ggrid, 256, GEMM_SMEM>>>(bias, m0);
        lep_kernel<<<MC, 192>>>(obs, m0);
    }

    scan_kernel<<<32, 64>>>();
    final_kernel<<<MTOT, 256>>>(seq);
    reduce_kernel<<<1, 256>>>(out);
}

// round 4
// speedup vs baseline: 4.0446x; 1.2497x over previous
#include <cuda_runtime.h>
#include <cuda_bf16.h>
#include <math.h>
#include <stdint.h>

#define TT 512
#define BB 16
#define HH 48
#define SS 4
#define OO 48
#define DD 768
#define NN 9216      /* S*H*O */
#define MTOT 8192    /* B*T */
#define NGROUP 192   /* S*H */

// ---------------- device scratch ----------------
__device__ __nv_bfloat16 g_emb16[MTOT * DD]; // 12.6 MB
__device__ __nv_bfloat16 g_w16[NN * DD];     // 14.2 MB
__device__ float g_val[MTOT * NGROUP];       // 6.3 MB  mixture value per (bt, s*48+h)
__device__ float g_lep[MTOT * HH];
__device__ float g_elep[MTOT * HH];
__device__ float g_log_alpha[MTOT * HH];
__device__ float g_log_beta[MTOT * HH];
__device__ float g_partial[MTOT];
__device__ float g_lp[HH];
__device__ float g_log_trans[HH * HH];
__device__ float g_trans_prob[HH * HH];
__device__ float g_emiss_prob[SS * HH * OO];

// ---------------- helpers ----------------
__device__ __forceinline__ uint32_t smem_u32(const void* p) {
    uint32_t a;
    asm("{ .reg .u64 t; cvta.to.shared.u64 t, %1; cvt.u32.u64 %0, t; }" : "=r"(a) : "l"(p));
    return a;
}

__device__ __forceinline__ float fexp(float x) {
    if (x < -87.0f) return 0.0f;
    float t = x * 1.4426950408889634f;
    float n = rintf(t);
    float f = t - n;
    float p = 1.5403530393381609e-4f;
    p = fmaf(p, f, 1.3333558146428443e-3f);
    p = fmaf(p, f, 9.6181291076284772e-3f);
    p = fmaf(p, f, 5.5504108664821580e-2f);
    p = fmaf(p, f, 2.4022650695910072e-1f);
    p = fmaf(p, f, 6.9314718055994531e-1f);
    p = fmaf(p, f, 1.0f);
    int e = (int)n;
    if (e < -126) return 0.0f;
    if (e > 126) e = 126;
    return p * __int_as_float((e + 127) << 23);
}

__device__ __forceinline__ float blockSum256(float v, float* red) {
    int tid = threadIdx.x;
#pragma unroll
    for (int o = 16; o > 0; o >>= 1) v += __shfl_down_sync(0xffffffffu, v, o);
    __syncthreads();
    if ((tid & 31) == 0) red[tid >> 5] = v;
    __syncthreads();
    if (tid < 32) {
        float r = (tid < 8) ? red[tid] : 0.0f;
#pragma unroll
        for (int o = 4; o > 0; o >>= 1) r += __shfl_down_sync(0xffffffffu, r, o);
        if (tid == 0) red[0] = r;
    }
    __syncthreads();
    return red[0];
}

__device__ __forceinline__ float blockMax256(float v, float* red) {
    int tid = threadIdx.x;
#pragma unroll
    for (int o = 16; o > 0; o >>= 1) v = fmaxf(v, __shfl_down_sync(0xffffffffu, v, o));
    __syncthreads();
    if ((tid & 31) == 0) red[tid >> 5] = v;
    __syncthreads();
    if (tid < 32) {
        float r = (tid < 8) ? red[tid] : -3.0e38f;
#pragma unroll
        for (int o = 4; o > 0; o >>= 1) r = fmaxf(r, __shfl_down_sync(0xffffffffu, r, o));
        if (tid == 0) red[0] = r;
    }
    __syncthreads();
    return red[0];
}

// ---------------- kernel 0: small preprocessing ----------------
__global__ void prep_kernel(const float* __restrict__ sp,
                            const float* __restrict__ ut,
                            const float* __restrict__ ue) {
    int tid = threadIdx.x;
    if (tid < HH) {
        const float* row = ut + tid * HH;
        float m = row[0];
#pragma unroll
        for (int j = 1; j < HH; j++) m = fmaxf(m, row[j]);
        float s = 0.0f;
#pragma unroll
        for (int j = 0; j < HH; j++) s += fexp(row[j] - m);
        float ls = logf(s) + m;
#pragma unroll
        for (int j = 0; j < HH; j++) {
            float v = row[j] - ls;
            g_log_trans[tid * HH + j] = v;
            g_trans_prob[tid * HH + j] = fexp(v);
        }
    }
    if (tid < SS * HH) {
        const float* row = ue + tid * OO;
        float m = row[0];
#pragma unroll
        for (int j = 1; j < OO; j++) m = fmaxf(m, row[j]);
        float s = 0.0f;
#pragma unroll
        for (int j = 0; j < OO; j++) s += fexp(row[j] - m);
        float inv = 1.0f / s;
#pragma unroll
        for (int j = 0; j < OO; j++) g_emiss_prob[tid * OO + j] = fexp(row[j] - m) * inv;
    }
    if (tid == 0) {
        float m = sp[0];
        for (int j = 1; j < HH; j++) m = fmaxf(m, sp[j]);
        float s = 0.0f;
        for (int j = 0; j < HH; j++) s += fexp(sp[j] - m);
        float ls = logf(s) + m;
        for (int j = 0; j < HH; j++) g_lp[j] = sp[j] - ls;
    }
}

// ---------------- kernel 0b: fp32 -> bf16 conversion ----------------
__global__ void __launch_bounds__(256) convert_kernel(const float* __restrict__ emb,
                                                      const float* __restrict__ Wm) {
    const int nA = MTOT * DD / 4;
    const int nW = NN * DD / 4;
    int i = blockIdx.x * 256 + threadIdx.x;
    if (i < nA) {
        float4 v = ((const float4*)emb)[i];
        __nv_bfloat162 lo = __floats2bfloat162_rn(v.x, v.y);
        __nv_bfloat162 hi = __floats2bfloat162_rn(v.z, v.w);
        ((__nv_bfloat162*)g_emb16)[i * 2] = lo;
        ((__nv_bfloat162*)g_emb16)[i * 2 + 1] = hi;
    } else if (i < nA + nW) {
        int j = i - nA;
        float4 v = ((const float4*)Wm)[j];
        __nv_bfloat162 lo = __floats2bfloat162_rn(v.x, v.y);
        __nv_bfloat162 hi = __floats2bfloat162_rn(v.z, v.w);
        ((__nv_bfloat162*)g_w16)[j * 2] = lo;
        ((__nv_bfloat162*)g_w16)[j * 2 + 1] = hi;
    }
}

// ---------------- kernel 1: fused bf16 GEMM (128x96) + softmax/mixture epilogue ----------------
// For each (bt row, group g): softmax over 48 logits, dot with obs, mix with
// table emissions; writes g_val[bt, g]. No logits buffer at all.
#define GEMM_SMEM 57344
__device__ __forceinline__ void cp_async16(uint32_t dst, const void* src) {
    asm volatile("cp.async.cg.shared.global [%0], [%1], 16;" ::
                 "r"(dst), "l"(__cvta_generic_to_global(src)));
}

__global__ void __launch_bounds__(256) mma_fused_kernel(const float* __restrict__ bias,
                                                        const float* __restrict__ obs) {
    extern __shared__ char smem[];
    float* smf = (float*)smem;
    uint32_t sbase = smem_u32(smem);
    const int tid = threadIdx.x;
    const int wid = tid >> 5, lane = tid & 31;
    const int bn = blockIdx.x * 96;           // N base (2 groups)
    const int bm = blockIdx.y * 128;          // M base (global bt)
    const int wm = (wid >> 1) * 32;           // warp M offset (0,32,64,96)
    const int gsel = wid & 1;                 // warp group select (0/1)
    const int wn = gsel * 48;

    // smem mainloop layout: A0 @0 (16K), A1 @16384, B0 @32768 (12K), B1 @45056
    const int sub = lane >> 3, l8 = lane & 7;
    const int a_row_in = (sub & 1) * 8 + l8;
    const int a_kb = (sub >> 1) * 16;
    const int b_row_in = (sub >> 1) * 8 + l8;
    const int b_kb = (sub & 1) * 16;

    uint32_t a_base[2], b_base[3];
    int a_xor[2], b_xor[3];
#pragma unroll
    for (int mi = 0; mi < 2; mi++) {
        int r = wm + mi * 16 + a_row_in;
        a_base[mi] = (uint32_t)(r * 128);
        a_xor[mi] = (r & 7) << 4;
    }
#pragma unroll
    for (int pi = 0; pi < 3; pi++) {
        int r = wn + pi * 16 + b_row_in;
        b_base[pi] = (uint32_t)(r * 128);
        b_xor[pi] = (r & 7) << 4;
    }

    float c[2][6][4];
#pragma unroll
    for (int mi = 0; mi < 2; mi++)
#pragma unroll
        for (int ni = 0; ni < 6; ni++)
#pragma unroll
            for (int q = 0; q < 4; q++) c[mi][ni][q] = 0.0f;

    auto load_tiles = [&](int kb, int buf) {
        uint32_t adst = sbase + (uint32_t)(buf * 16384);
        uint32_t bdst = sbase + 32768u + (uint32_t)(buf * 12288);
#pragma unroll
        for (int p = 0; p < 4; p++) {
            int idx = tid + p * 256;
            int r = idx >> 3, cc = idx & 7;
            uint32_t off = (uint32_t)(r * 128 + cc * 16);
            off ^= (uint32_t)((r & 7) << 4);
            cp_async16(adst + off, g_emb16 + (size_t)(bm + r) * DD + kb * 64 + cc * 8);
        }
#pragma unroll
        for (int p = 0; p < 3; p++) {
            int idx = tid + p * 256;
            int r = idx >> 3, cc = idx & 7;
            uint32_t off = (uint32_t)(r * 128 + cc * 16);
            off ^= (uint32_t)((r & 7) << 4);
            cp_async16(bdst + off, g_w16 + (size_t)(bn + r) * DD + kb * 64 + cc * 8);
        }
        asm volatile("cp.async.commit_group;" ::: "memory");
    };

    load_tiles(0, 0);
    load_tiles(1, 1);

    for (int kb = 0; kb < 12; kb++) {
        int buf = kb & 1;
        if (kb < 11) asm volatile("cp.async.wait_group 1;" ::: "memory");
        else         asm volatile("cp.async.wait_group 0;" ::: "memory");
        __syncthreads();

        uint32_t abuf = sbase + (uint32_t)(buf * 16384);
        uint32_t bbuf = sbase + 32768u + (uint32_t)(buf * 12288);
#pragma unroll
        for (int ks = 0; ks < 4; ks++) {
            uint32_t a[2][4];
#pragma unroll
            for (int mi = 0; mi < 2; mi++) {
                uint32_t addr = abuf + a_base[mi] + (uint32_t)((ks * 32 + a_kb) ^ a_xor[mi]);
                asm volatile("ldmatrix.sync.aligned.m8n8.x4.shared.b16 {%0,%1,%2,%3}, [%4];"
                             : "=r"(a[mi][0]), "=r"(a[mi][1]), "=r"(a[mi][2]), "=r"(a[mi][3])
                             : "r"(addr));
            }
            uint32_t b[6][2];
#pragma unroll
            for (int pi = 0; pi < 3; pi++) {
                uint32_t addr = bbuf + b_base[pi] + (uint32_t)((ks * 32 + b_kb) ^ b_xor[pi]);
                uint32_t r0, r1, r2, r3;
                asm volatile("ldmatrix.sync.aligned.m8n8.x4.shared.b16 {%0,%1,%2,%3}, [%4];"
                             : "=r"(r0), "=r"(r1), "=r"(r2), "=r"(r3) : "r"(addr));
                b[pi * 2][0] = r0; b[pi * 2][1] = r1;
                b[pi * 2 + 1][0] = r2; b[pi * 2 + 1][1] = r3;
            }
#pragma unroll
            for (int mi = 0; mi < 2; mi++)
#pragma unroll
                for (int ni = 0; ni < 6; ni++) {
                    asm volatile(
                        "mma.sync.aligned.m16n8k16.row.col.f32.bf16.bf16.f32 "
                        "{%0,%1,%2,%3}, {%4,%5,%6,%7}, {%8,%9}, {%0,%1,%2,%3};"
                        : "+f"(c[mi][ni][0]), "+f"(c[mi][ni][1]),
                          "+f"(c[mi][ni][2]), "+f"(c[mi][ni][3])
                        : "r"(a[mi][0]), "r"(a[mi][1]), "r"(a[mi][2]), "r"(a[mi][3]),
                          "r"(b[ni][0]), "r"(b[ni][1]));
                }
        }
        __syncthreads();
        if (kb + 2 < 12) load_tiles(kb + 2, buf);
    }

    // ---------------- fused epilogue ----------------
    // reload smem: obs tile [128 rows x 48, padded 50] @0, emiss rows @ float idx 6400
    const int g0 = blockIdx.x * 2;
    const int s_src = g0 / HH;
    const int EPOFF = 6400;
    __syncthreads();
    for (int i = tid; i < 128 * 24; i += 256) {
        int r = i / 24, c2 = i - r * 24;
        float2 v = *(const float2*)&obs[((size_t)(bm + r) * SS + s_src) * OO + c2 * 2];
        *(float2*)&smf[r * 50 + c2 * 2] = v;
    }
    if (tid < 96) smf[EPOFF + tid] = g_emiss_prob[g0 * 48 + tid];
    __syncthreads();

    const int trow = lane >> 2;          // 0..7
    const int tcol = (lane & 3) * 2;     // 0,2,4,6
    const int ggl = g0 + gsel;           // global group index

    float bx[6], by[6];
#pragma unroll
    for (int ni = 0; ni < 6; ni++) {
        float2 bv = *(const float2*)&bias[bn + wn + ni * 8 + tcol];
        bx[ni] = bv.x; by[ni] = bv.y;
    }
    float epx[6], epy[6];
#pragma unroll
    for (int ni = 0; ni < 6; ni++) {
        epx[ni] = smf[EPOFF + gsel * 48 + ni * 8 + tcol];
        epy[ni] = smf[EPOFF + gsel * 48 + ni * 8 + tcol + 1];
    }

#pragma unroll
    for (int mi = 0; mi < 2; mi++) {
#pragma unroll
        for (int half = 0; half < 2; half++) {
            int rt = wm + mi * 16 + half * 8 + trow;   // row in tile
            float vx[6], vy[6];
            float mx = -3.0e38f;
#pragma unroll
            for (int ni = 0; ni < 6; ni++) {
                vx[ni] = c[mi][ni][half * 2] + bx[ni];
                vy[ni] = c[mi][ni][half * 2 + 1] + by[ni];
                mx = fmaxf(mx, fmaxf(vx[ni], vy[ni]));
            }
            mx = fmaxf(mx, __shfl_xor_sync(0xffffffffu, mx, 1));
            mx = fmaxf(mx, __shfl_xor_sync(0xffffffffu, mx, 2));
            float den = 0.0f, dot = 0.0f, eo = 0.0f;
            const float* obr = &smf[rt * 50];
#pragma unroll
            for (int ni = 0; ni < 6; ni++) {
                float obx = obr[ni * 8 + tcol];
                float oby = obr[ni * 8 + tcol + 1];
                float ex = fexp(vx[ni] - mx);
                float ey = fexp(vy[ni] - mx);
                den += ex + ey;
                dot = fmaf(ex, obx, dot);
                dot = fmaf(ey, oby, dot);
                eo = fmaf(epx[ni], obx, eo);
                eo = fmaf(epy[ni], oby, eo);
            }
#pragma unroll
            for (int m = 1; m <= 2; m <<= 1) {
                den += __shfl_xor_sync(0xffffffffu, den, m);
                dot += __shfl_xor_sync(0xffffffffu, dot, m);
                eo  += __shfl_xor_sync(0xffffffffu, eo, m);
            }
            if ((lane & 3) == 0) {
                float val = 0.5f * eo + 0.5f * (dot / den);
                g_val[(size_t)(bm + rt) * NGROUP + ggl] = val;
            }
        }
    }
}

// ---------------- kernel 1b: combine 4 sources -> elep/lep ----------------
__global__ void __launch_bounds__(256) combine_kernel() {
    int idx = blockIdx.x * 256 + threadIdx.x;   // bt*48 + h
    if (idx >= MTOT * HH) return;
    int bt = idx / HH, h = idx - bt * HH;
    const float* v = g_val + (size_t)bt * NGROUP + h;
    float p = v[0] * v[48] * v[96] * v[144];
    g_elep[idx] = p;
    g_lep[idx] = logf(p);
}

// ---------------- kernel 3: forward+backward scans ----------------
__global__ void __launch_bounds__(64) scan_kernel() {
    __shared__ float tp[HH * HH];
    __shared__ float vec[HH];
    __shared__ float wbuf[HH];
    __shared__ float ubuf[HH];
    __shared__ float ssum;
    int tid = threadIdx.x;
    int b = blockIdx.x & 15;
    bool fwd = blockIdx.x < 16;

    if (fwd) {
        for (int i = tid; i < HH * HH; i += 64) tp[i] = g_trans_prob[i];
        if (tid < HH) wbuf[tid] = fexp(g_lp[tid]) * g_elep[(size_t)(b * TT) * HH + tid];
        __syncthreads();
        if (tid < 32) {
            float r = wbuf[tid] + ((tid < 16) ? wbuf[tid + 32] : 0.0f);
#pragma unroll
            for (int o = 16; o > 0; o >>= 1) r += __shfl_down_sync(0xffffffffu, r, o);
            if (tid == 0) ssum = r;
        }
        __syncthreads();
        if (tid < HH) {
            float a = wbuf[tid] / ssum;
            vec[tid] = a;
            g_log_alpha[(size_t)(b * TT) * HH + tid] = logf(a);
        }
        __syncthreads();
        for (int t = 1; t < TT; t++) {
            float el = (tid < HH) ? g_elep[(size_t)(b * TT + t) * HH + tid] : 0.0f;
            if (tid < HH) {
                float v0 = 0, v1 = 0, v2 = 0, v3 = 0;
#pragma unroll
                for (int i = 0; i < HH; i += 4) {
                    v0 = fmaf(vec[i + 0], tp[(i + 0) * HH + tid], v0);
                    v1 = fmaf(vec[i + 1], tp[(i + 1) * HH + tid], v1);
                    v2 = fmaf(vec[i + 2], tp[(i + 2) * HH + tid], v2);
                    v3 = fmaf(vec[i + 3], tp[(i + 3) * HH + tid], v3);
                }
                wbuf[tid] = (v0 + v1 + v2 + v3) * el;
            }
            __syncthreads();
            if (tid < 32) {
                float r = wbuf[tid] + ((tid < 16) ? wbuf[tid + 32] : 0.0f);
#pragma unroll
                for (int o = 16; o > 0; o >>= 1) r += __shfl_down_sync(0xffffffffu, r, o);
                if (tid == 0) ssum = r;
            }
            __syncthreads();
            if (tid < HH) {
                float a = wbuf[tid] / ssum;
                vec[tid] = a;
                g_log_alpha[(size_t)(b * TT + t) * HH + tid] = logf(a);
            }
            __syncthreads();
        }
    } else {
        for (int idx = tid; idx < HH * HH; idx += 64) {
            int i = idx / HH, j = idx - i * HH;
            tp[j * HH + i] = g_trans_prob[idx];
        }
        if (tid < HH) {
            vec[tid] = 1.0f;
            g_log_beta[(size_t)(b * TT + TT - 1) * HH + tid] = 0.0f;
        }
        __syncthreads();
        for (int t = TT - 2; t >= 0; t--) {
            if (tid < HH) ubuf[tid] = g_elep[(size_t)(b * TT + t) * HH + tid] * vec[tid];
            __syncthreads();
            if (tid < HH) {
                float v0 = 0, v1 = 0, v2 = 0, v3 = 0;
#pragma unroll
                for (int j = 0; j < HH; j += 4) {
                    v0 = fmaf(tp[(j + 0) * HH + tid], ubuf[j + 0], v0);
                    v1 = fmaf(tp[(j + 1) * HH + tid], ubuf[j + 1], v1);
                    v2 = fmaf(tp[(j + 2) * HH + tid], ubuf[j + 2], v2);
                    v3 = fmaf(tp[(j + 3) * HH + tid], ubuf[j + 3], v3);
                }
                wbuf[tid] = v0 + v1 + v2 + v3;
            }
            __syncthreads();
            if (tid < 32) {
                float r = wbuf[tid] + ((tid < 16) ? wbuf[tid + 32] : 0.0f);
#pragma unroll
                for (int o = 16; o > 0; o >>= 1) r += __shfl_down_sync(0xffffffffu, r, o);
                if (tid == 0) ssum = r;
            }
            __syncthreads();
            if (tid < HH) {
                float bb = wbuf[tid] / ssum;
                vec[tid] = bb;
                g_log_beta[(size_t)(b * TT + t) * HH + tid] = logf(bb);
            }
            __syncthreads();
        }
    }
}

// ---------------- kernel 4: per-(b,t) gamma / prior / xi terms ----------------
__global__ void __launch_bounds__(256) final_kernel(const int* __restrict__ seq) {
    __shared__ float lt[HH * HH];
    __shared__ float sA[HH], sB[HH], sG[HH], sL[HH];
    __shared__ float red[32];
    int tid = threadIdx.x;
    int bt = blockIdx.x;
    int b = bt >> 9;
    int t = bt & (TT - 1);
    int len = seq[b];

    for (int i = tid; i < HH * HH; i += 256) lt[i] = g_log_trans[i];
    if (tid < HH) {
        int tb = (t + TT - len) & (TT - 1);
        float br = g_log_beta[(size_t)(b * TT + tb) * HH + tid];
        float at = g_log_alpha[(size_t)(b * TT + t) * HH + tid];
        float lpv = g_lep[(size_t)(b * TT + t) * HH + tid];
        sG[tid] = at + br;
        sB[tid] = lpv + br;
        sL[tid] = lpv;
        sA[tid] = (t > 0) ? g_log_alpha[(size_t)(b * TT + t - 1) * HH + tid] : 0.0f;
    }
    __syncthreads();

    float gv = (tid < HH) ? sG[tid] : -3.0e38f;
    float M1 = blockMax256(gv, red);
    float e = (tid < HH) ? fexp(sG[tid] - M1) : 0.0f;
    float Z = blockSum256(e, red);
    float E = blockSum256(e * ((tid < HH) ? sL[tid] : 0.0f), red);
    float total = 0.0f;
    if (t < len) total += E / Z;
    if (t == 0) {
        float P = blockSum256(e * ((tid < HH) ? g_lp[tid] : 0.0f), red);
        total += P / Z;
    }

    if (t >= 1 && t < len) {
        float lm = -3.0e38f;
        for (int idx = tid; idx < HH * HH; idx += 256) {
            int i = idx / HH, j = idx - i * HH;
            lm = fmaxf(lm, lt[idx] + sA[i] + sB[j]);
        }
        float M2 = blockMax256(lm, red);
        float z = 0.0f, w = 0.0f;
        for (int idx = tid; idx < HH * HH; idx += 256) {
            int i = idx / HH, j = idx - i * HH;
            float ltv = lt[idx];
            float ex = fexp(ltv + sA[i] + sB[j] - M2);
            z += ex;
            w = fmaf(ex, ltv, w);
        }
        float Z2 = blockSum256(z, red);
        float W2 = blockSum256(w, red);
        total += W2 / Z2;
    }
    if (tid == 0) g_partial[bt] = total;
}

// ---------------- kernel 5: deterministic final reduction ----------------
__global__ void __launch_bounds__(256) reduce_kernel(float* __restrict__ out) {
    __shared__ float red[256];
    int tid = threadIdx.x;
    float s = 0.0f;
    for (int i = tid; i < MTOT; i += 256) s += g_partial[i];
    red[tid] = s;
    __syncthreads();
    for (int off = 128; off > 0; off >>= 1) {
        if (tid < off) red[tid] += red[tid + off];
        __syncthreads();
    }
    if (tid == 0) out[0] = red[0] * (1.0f / (float)BB);
}

// ---------------- launch ----------------
extern "C" void kernel_launch(void* const* d_in, const int* in_sizes, int n_in,
                              void* d_out, int out_size) {
    const float* emb  = (const float*)d_in[0];
    const float* obs  = (const float*)d_in[1];
    const float* sp   = (const float*)d_in[2];
    const float* ut   = (const float*)d_in[3];
    const float* ue   = (const float*)d_in[4];
    const float* Wm   = (const float*)d_in[5];
    const float* bias = (const float*)d_in[6];
    const int*   seq  = (const int*)d_in[7];
    float* out = (float*)d_out;

    cudaFuncSetAttribute(mma_fused_kernel, cudaFuncAttributeMaxDynamicSharedMemorySize, GEMM_SMEM);

    prep_kernel<<<1, 192>>>(sp, ut, ue);
    {
        const int nA = MTOT * DD / 4, nW = NN * DD / 4;
        convert_kernel<<<(nA + nW + 255) / 256, 256>>>(emb, Wm);
    }

    dim3 ggrid(NN / 96, MTOT / 128);
    mma_fused_kernel<<<ggrid, 256, GEMM_SMEM>>>(bias, obs);
    combine_kernel<<<(MTOT * HH + 255) / 256, 256>>>();

    scan_kernel<<<32, 64>>>();
    final_kernel<<<MTOT, 256>>>(seq);
    reduce_kernel<<<1, 256>>>(out);
}

// round 5
// speedup vs baseline: 4.0818x; 1.0092x over previous
#include <cuda_runtime.h>
#include <cuda_bf16.h>
#include <math.h>
#include <stdint.h>

#define TT 512
#define BB 16
#define HH 48
#define SS 4
#define OO 48
#define DD 768
#define NN 9216      /* S*H*O */
#define MTOT 8192    /* B*T */
#define NGROUP 192   /* S*H */

// ---------------- device scratch ----------------
__device__ __nv_bfloat16 g_emb16[MTOT * DD]; // 12.6 MB
__device__ __nv_bfloat16 g_w16[NN * DD];     // 14.2 MB
__device__ float g_val[MTOT * NGROUP];       // 6.3 MB
__device__ float g_lep[MTOT * HH];
__device__ float g_elep[MTOT * HH];
__device__ float g_alpha[MTOT * HH];         // prob-space alpha (normalized)
__device__ float g_beta[MTOT * HH];          // prob-space beta (per-step normalized)
__device__ float g_partial[MTOT];
__device__ float g_lp[HH];
__device__ float g_log_trans[HH * HH];
__device__ float g_trans_prob[HH * HH];
__device__ float g_emiss_prob[SS * HH * OO];

// ---------------- helpers ----------------
__device__ __forceinline__ uint32_t smem_u32(const void* p) {
    uint32_t a;
    asm("{ .reg .u64 t; cvta.to.shared.u64 t, %1; cvt.u32.u64 %0, t; }" : "=r"(a) : "l"(p));
    return a;
}

__device__ __forceinline__ float fexp(float x) {
    if (x < -87.0f) return 0.0f;
    float t = x * 1.4426950408889634f;
    float n = rintf(t);
    float f = t - n;
    float p = 1.5403530393381609e-4f;
    p = fmaf(p, f, 1.3333558146428443e-3f);
    p = fmaf(p, f, 9.6181291076284772e-3f);
    p = fmaf(p, f, 5.5504108664821580e-2f);
    p = fmaf(p, f, 2.4022650695910072e-1f);
    p = fmaf(p, f, 6.9314718055994531e-1f);
    p = fmaf(p, f, 1.0f);
    int e = (int)n;
    if (e < -126) return 0.0f;
    if (e > 126) e = 126;
    return p * __int_as_float((e + 127) << 23);
}

__device__ __forceinline__ float blockSum256(float v, float* red) {
    int tid = threadIdx.x;
#pragma unroll
    for (int o = 16; o > 0; o >>= 1) v += __shfl_down_sync(0xffffffffu, v, o);
    __syncthreads();
    if ((tid & 31) == 0) red[tid >> 5] = v;
    __syncthreads();
    if (tid < 32) {
        float r = (tid < 8) ? red[tid] : 0.0f;
#pragma unroll
        for (int o = 4; o > 0; o >>= 1) r += __shfl_down_sync(0xffffffffu, r, o);
        if (tid == 0) red[0] = r;
    }
    __syncthreads();
    return red[0];
}

// ---------------- kernel 0: small preprocessing ----------------
__global__ void prep_kernel(const float* __restrict__ sp,
                            const float* __restrict__ ut,
                            const float* __restrict__ ue) {
    int tid = threadIdx.x;
    if (tid < HH) {
        const float* row = ut + tid * HH;
        float m = row[0];
#pragma unroll
        for (int j = 1; j < HH; j++) m = fmaxf(m, row[j]);
        float s = 0.0f;
#pragma unroll
        for (int j = 0; j < HH; j++) s += fexp(row[j] - m);
        float ls = logf(s) + m;
#pragma unroll
        for (int j = 0; j < HH; j++) {
            float v = row[j] - ls;
            g_log_trans[tid * HH + j] = v;
            g_trans_prob[tid * HH + j] = fexp(v);
        }
    }
    if (tid < SS * HH) {
        const float* row = ue + tid * OO;
        float m = row[0];
#pragma unroll
        for (int j = 1; j < OO; j++) m = fmaxf(m, row[j]);
        float s = 0.0f;
#pragma unroll
        for (int j = 0; j < OO; j++) s += fexp(row[j] - m);
        float inv = 1.0f / s;
#pragma unroll
        for (int j = 0; j < OO; j++) g_emiss_prob[tid * OO + j] = fexp(row[j] - m) * inv;
    }
    if (tid == 0) {
        float m = sp[0];
        for (int j = 1; j < HH; j++) m = fmaxf(m, sp[j]);
        float s = 0.0f;
        for (int j = 0; j < HH; j++) s += fexp(sp[j] - m);
        float ls = logf(s) + m;
        for (int j = 0; j < HH; j++) g_lp[j] = sp[j] - ls;
    }
}

// ---------------- kernel 0b: fp32 -> bf16 conversion ----------------
__global__ void __launch_bounds__(256) convert_kernel(const float* __restrict__ emb,
                                                      const float* __restrict__ Wm) {
    const int nA = MTOT * DD / 4;
    const int nW = NN * DD / 4;
    int i = blockIdx.x * 256 + threadIdx.x;
    if (i < nA) {
        float4 v = ((const float4*)emb)[i];
        __nv_bfloat162 lo = __floats2bfloat162_rn(v.x, v.y);
        __nv_bfloat162 hi = __floats2bfloat162_rn(v.z, v.w);
        ((__nv_bfloat162*)g_emb16)[i * 2] = lo;
        ((__nv_bfloat162*)g_emb16)[i * 2 + 1] = hi;
    } else if (i < nA + nW) {
        int j = i - nA;
        float4 v = ((const float4*)Wm)[j];
        __nv_bfloat162 lo = __floats2bfloat162_rn(v.x, v.y);
        __nv_bfloat162 hi = __floats2bfloat162_rn(v.z, v.w);
        ((__nv_bfloat162*)g_w16)[j * 2] = lo;
        ((__nv_bfloat162*)g_w16)[j * 2 + 1] = hi;
    }
}

// ---------------- kernel 1: fused bf16 GEMM (128x192, 512 thr, 4-stage) ----------------
#define STAGE_BYTES 40960            /* A 16384 + B 24576 */
#define GEMM_SMEM (4 * STAGE_BYTES)  /* 163840 */
__device__ __forceinline__ void cp_async16(uint32_t dst, const void* src) {
    asm volatile("cp.async.cg.shared.global [%0], [%1], 16;" ::
                 "r"(dst), "l"(__cvta_generic_to_global(src)));
}

__global__ void __launch_bounds__(512) mma_fused_kernel(const float* __restrict__ bias,
                                                        const float* __restrict__ obs) {
    extern __shared__ char smem[];
    float* smf = (float*)smem;
    uint32_t sbase = smem_u32(smem);
    const int tid = threadIdx.x;
    const int wid = tid >> 5, lane = tid & 31;
    const int bn = blockIdx.x * 192;          // N base (4 groups)
    const int bm = blockIdx.y * 128;          // M base
    const int wm = (wid >> 2) * 32;           // warp M offset (0,32,64,96)
    const int gsel = wid & 3;                 // warp group select (0..3)
    const int wn = gsel * 48;

    const int sub = lane >> 3, l8 = lane & 7;
    const int a_row_in = (sub & 1) * 8 + l8;
    const int a_kb = (sub >> 1) * 16;
    const int b_row_in = (sub >> 1) * 8 + l8;
    const int b_kb = (sub & 1) * 16;

    uint32_t a_base[2], b_base[3];
    int a_xor[2], b_xor[3];
#pragma unroll
    for (int mi = 0; mi < 2; mi++) {
        int r = wm + mi * 16 + a_row_in;
        a_base[mi] = (uint32_t)(r * 128);
        a_xor[mi] = (r & 7) << 4;
    }
#pragma unroll
    for (int pi = 0; pi < 3; pi++) {
        int r = wn + pi * 16 + b_row_in;
        b_base[pi] = (uint32_t)(r * 128);
        b_xor[pi] = (r & 7) << 4;
    }

    float c[2][6][4];
#pragma unroll
    for (int mi = 0; mi < 2; mi++)
#pragma unroll
        for (int ni = 0; ni < 6; ni++)
#pragma unroll
            for (int q = 0; q < 4; q++) c[mi][ni][q] = 0.0f;

    auto load_tiles = [&](int kb, int stage) {
        uint32_t adst = sbase + (uint32_t)(stage * STAGE_BYTES);
        uint32_t bdst = adst + 16384u;
#pragma unroll
        for (int p = 0; p < 2; p++) {
            int idx = tid + p * 512;
            int r = idx >> 3, cc = idx & 7;
            uint32_t off = (uint32_t)(r * 128 + cc * 16);
            off ^= (uint32_t)((r & 7) << 4);
            cp_async16(adst + off, g_emb16 + (size_t)(bm + r) * DD + kb * 64 + cc * 8);
        }
#pragma unroll
        for (int p = 0; p < 3; p++) {
            int idx = tid + p * 512;
            int r = idx >> 3, cc = idx & 7;
            uint32_t off = (uint32_t)(r * 128 + cc * 16);
            off ^= (uint32_t)((r & 7) << 4);
            cp_async16(bdst + off, g_w16 + (size_t)(bn + r) * DD + kb * 64 + cc * 8);
        }
        asm volatile("cp.async.commit_group;" ::: "memory");
    };

    load_tiles(0, 0);
    load_tiles(1, 1);
    load_tiles(2, 2);

    for (int kb = 0; kb < 12; kb++) {
        if (kb <= 9)       asm volatile("cp.async.wait_group 2;" ::: "memory");
        else if (kb == 10) asm volatile("cp.async.wait_group 1;" ::: "memory");
        else               asm volatile("cp.async.wait_group 0;" ::: "memory");
        __syncthreads();
        if (kb + 3 < 12) load_tiles(kb + 3, (kb + 3) & 3);

        uint32_t abuf = sbase + (uint32_t)((kb & 3) * STAGE_BYTES);
        uint32_t bbuf = abuf + 16384u;
#pragma unroll
        for (int ks = 0; ks < 4; ks++) {
            uint32_t a[2][4];
#pragma unroll
            for (int mi = 0; mi < 2; mi++) {
                uint32_t addr = abuf + a_base[mi] + (uint32_t)((ks * 32 + a_kb) ^ a_xor[mi]);
                asm volatile("ldmatrix.sync.aligned.m8n8.x4.shared.b16 {%0,%1,%2,%3}, [%4];"
                             : "=r"(a[mi][0]), "=r"(a[mi][1]), "=r"(a[mi][2]), "=r"(a[mi][3])
                             : "r"(addr));
            }
            uint32_t b[6][2];
#pragma unroll
            for (int pi = 0; pi < 3; pi++) {
                uint32_t addr = bbuf + b_base[pi] + (uint32_t)((ks * 32 + b_kb) ^ b_xor[pi]);
                uint32_t r0, r1, r2, r3;
                asm volatile("ldmatrix.sync.aligned.m8n8.x4.shared.b16 {%0,%1,%2,%3}, [%4];"
                             : "=r"(r0), "=r"(r1), "=r"(r2), "=r"(r3) : "r"(addr));
                b[pi * 2][0] = r0; b[pi * 2][1] = r1;
                b[pi * 2 + 1][0] = r2; b[pi * 2 + 1][1] = r3;
            }
#pragma unroll
            for (int mi = 0; mi < 2; mi++)
#pragma unroll
                for (int ni = 0; ni < 6; ni++) {
                    asm volatile(
                        "mma.sync.aligned.m16n8k16.row.col.f32.bf16.bf16.f32 "
                        "{%0,%1,%2,%3}, {%4,%5,%6,%7}, {%8,%9}, {%0,%1,%2,%3};"
                        : "+f"(c[mi][ni][0]), "+f"(c[mi][ni][1]),
                          "+f"(c[mi][ni][2]), "+f"(c[mi][ni][3])
                        : "r"(a[mi][0]), "r"(a[mi][1]), "r"(a[mi][2]), "r"(a[mi][3]),
                          "r"(b[ni][0]), "r"(b[ni][1]));
                }
        }
    }

    // ---------------- fused epilogue ----------------
    const int g0 = blockIdx.x * 4;
    const int s_src = g0 / HH;
    const int EPOFF = 6400;
    __syncthreads();
    for (int i = tid; i < 128 * 24; i += 512) {
        int r = i / 24, c2 = i - r * 24;
        float2 v = *(const float2*)&obs[((size_t)(bm + r) * SS + s_src) * OO + c2 * 2];
        *(float2*)&smf[r * 50 + c2 * 2] = v;
    }
    if (tid < NGROUP) smf[EPOFF + tid] = g_emiss_prob[g0 * 48 + tid];
    __syncthreads();

    const int trow = lane >> 2;
    const int tcol = (lane & 3) * 2;
    const int ggl = g0 + gsel;

    float bx[6], by[6];
#pragma unroll
    for (int ni = 0; ni < 6; ni++) {
        float2 bv = *(const float2*)&bias[bn + wn + ni * 8 + tcol];
        bx[ni] = bv.x; by[ni] = bv.y;
    }
    float epx[6], epy[6];
#pragma unroll
    for (int ni = 0; ni < 6; ni++) {
        epx[ni] = smf[EPOFF + gsel * 48 + ni * 8 + tcol];
        epy[ni] = smf[EPOFF + gsel * 48 + ni * 8 + tcol + 1];
    }

#pragma unroll
    for (int mi = 0; mi < 2; mi++) {
#pragma unroll
        for (int half = 0; half < 2; half++) {
            int rt = wm + mi * 16 + half * 8 + trow;
            float vx[6], vy[6];
            float mx = -3.0e38f;
#pragma unroll
            for (int ni = 0; ni < 6; ni++) {
                vx[ni] = c[mi][ni][half * 2] + bx[ni];
                vy[ni] = c[mi][ni][half * 2 + 1] + by[ni];
                mx = fmaxf(mx, fmaxf(vx[ni], vy[ni]));
            }
            mx = fmaxf(mx, __shfl_xor_sync(0xffffffffu, mx, 1));
            mx = fmaxf(mx, __shfl_xor_sync(0xffffffffu, mx, 2));
            float den = 0.0f, dot = 0.0f, eo = 0.0f;
            const float* obr = &smf[rt * 50];
#pragma unroll
            for (int ni = 0; ni < 6; ni++) {
                float obx = obr[ni * 8 + tcol];
                float oby = obr[ni * 8 + tcol + 1];
                float ex = fexp(vx[ni] - mx);
                float ey = fexp(vy[ni] - mx);
                den += ex + ey;
                dot = fmaf(ex, obx, dot);
                dot = fmaf(ey, oby, dot);
                eo = fmaf(epx[ni], obx, eo);
                eo = fmaf(epy[ni], oby, eo);
            }
#pragma unroll
            for (int m = 1; m <= 2; m <<= 1) {
                den += __shfl_xor_sync(0xffffffffu, den, m);
                dot += __shfl_xor_sync(0xffffffffu, dot, m);
                eo  += __shfl_xor_sync(0xffffffffu, eo, m);
            }
            if ((lane & 3) == 0) {
                float val = 0.5f * eo + 0.5f * (dot / den);
                g_val[(size_t)(bm + rt) * NGROUP + ggl] = val;
            }
        }
    }
}

// ---------------- kernel 1b: combine 4 sources -> elep/lep ----------------
__global__ void __launch_bounds__(256) combine_kernel() {
    int idx = blockIdx.x * 256 + threadIdx.x;
    if (idx >= MTOT * HH) return;
    int bt = idx / HH, h = idx - bt * HH;
    const float* v = g_val + (size_t)bt * NGROUP + h;
    float p = v[0] * v[48] * v[96] * v[144];
    g_elep[idx] = p;
    g_lep[idx] = logf(p);
}

// ---------------- kernel 3: forward+backward scans (prob space) ----------------
__global__ void __launch_bounds__(64) scan_kernel() {
    __shared__ float tp[HH * HH];
    __shared__ float vec[HH];
    __shared__ float wbuf[HH];
    __shared__ float ubuf[HH];
    __shared__ float ssum;
    int tid = threadIdx.x;
    int b = blockIdx.x & 15;
    bool fwd = blockIdx.x < 16;

    if (fwd) {
        for (int i = tid; i < HH * HH; i += 64) tp[i] = g_trans_prob[i];
        if (tid < HH) wbuf[tid] = fexp(g_lp[tid]) * g_elep[(size_t)(b * TT) * HH + tid];
        __syncthreads();
        if (tid < 32) {
            float r = wbuf[tid] + ((tid < 16) ? wbuf[tid + 32] : 0.0f);
#pragma unroll
            for (int o = 16; o > 0; o >>= 1) r += __shfl_down_sync(0xffffffffu, r, o);
            if (tid == 0) ssum = r;
        }
        __syncthreads();
        if (tid < HH) {
            float a = wbuf[tid] / ssum;
            vec[tid] = a;
            g_alpha[(size_t)(b * TT) * HH + tid] = a;
        }
        __syncthreads();
        for (int t = 1; t < TT; t++) {
            float el = (tid < HH) ? g_elep[(size_t)(b * TT + t) * HH + tid] : 0.0f;
            if (tid < HH) {
                float v0 = 0, v1 = 0, v2 = 0, v3 = 0;
#pragma unroll
                for (int i = 0; i < HH; i += 4) {
                    v0 = fmaf(vec[i + 0], tp[(i + 0) * HH + tid], v0);
                    v1 = fmaf(vec[i + 1], tp[(i + 1) * HH + tid], v1);
                    v2 = fmaf(vec[i + 2], tp[(i + 2) * HH + tid], v2);
                    v3 = fmaf(vec[i + 3], tp[(i + 3) * HH + tid], v3);
                }
                wbuf[tid] = (v0 + v1 + v2 + v3) * el;
            }
            __syncthreads();
            if (tid < 32) {
                float r = wbuf[tid] + ((tid < 16) ? wbuf[tid + 32] : 0.0f);
#pragma unroll
                for (int o = 16; o > 0; o >>= 1) r += __shfl_down_sync(0xffffffffu, r, o);
                if (tid == 0) ssum = r;
            }
            __syncthreads();
            if (tid < HH) {
                float a = wbuf[tid] / ssum;
                vec[tid] = a;
                g_alpha[(size_t)(b * TT + t) * HH + tid] = a;
            }
            __syncthreads();
        }
    } else {
        for (int idx = tid; idx < HH * HH; idx += 64) {
            int i = idx / HH, j = idx - i * HH;
            tp[j * HH + i] = g_trans_prob[idx];
        }
        if (tid < HH) {
            vec[tid] = 1.0f;
            g_beta[(size_t)(b * TT + TT - 1) * HH + tid] = 1.0f;
        }
        __syncthreads();
        for (int t = TT - 2; t >= 0; t--) {
            if (tid < HH) ubuf[tid] = g_elep[(size_t)(b * TT + t) * HH + tid] * vec[tid];
            __syncthreads();
            if (tid < HH) {
                float v0 = 0, v1 = 0, v2 = 0, v3 = 0;
#pragma unroll
                for (int j = 0; j < HH; j += 4) {
                    v0 = fmaf(tp[(j + 0) * HH + tid], ubuf[j + 0], v0);
                    v1 = fmaf(tp[(j + 1) * HH + tid], ubuf[j + 1], v1);
                    v2 = fmaf(tp[(j + 2) * HH + tid], ubuf[j + 2], v2);
                    v3 = fmaf(tp[(j + 3) * HH + tid], ubuf[j + 3], v3);
                }
                wbuf[tid] = v0 + v1 + v2 + v3;
            }
            __syncthreads();
            if (tid < 32) {
                float r = wbuf[tid] + ((tid < 16) ? wbuf[tid + 32] : 0.0f);
#pragma unroll
                for (int o = 16; o > 0; o >>= 1) r += __shfl_down_sync(0xffffffffu, r, o);
                if (tid == 0) ssum = r;
            }
            __syncthreads();
            if (tid < HH) {
                float bb = wbuf[tid] / ssum;
                vec[tid] = bb;
                g_beta[(size_t)(b * TT + t) * HH + tid] = bb;
            }
            __syncthreads();
        }
    }
}

// ---------------- kernel 4: per-(b,t) gamma / prior / xi terms (prob space) ----------------
__global__ void __launch_bounds__(256) final_kernel(const int* __restrict__ seq) {
    __shared__ float lt[HH * HH];
    __shared__ float tp[HH * HH];
    __shared__ float sA[HH], sU[HH], sG[HH], sL[HH];
    __shared__ float red[32];
    int tid = threadIdx.x;
    int bt = blockIdx.x;
    int b = bt >> 9;
    int t = bt & (TT - 1);
    int len = seq[b];
    bool do_xi = (t >= 1 && t < len);

    for (int i = tid; i < HH * HH; i += 256) {
        lt[i] = g_log_trans[i];
        tp[i] = g_trans_prob[i];
    }
    if (tid < HH) {
        int tb = (t + TT - len) & (TT - 1);
        float br = g_beta[(size_t)(b * TT + tb) * HH + tid];
        float at = g_alpha[(size_t)(b * TT + t) * HH + tid];
        float lpv = g_lep[(size_t)(b * TT + t) * HH + tid];
        float el = g_elep[(size_t)(b * TT + t) * HH + tid];
        sG[tid] = at * br;
        sU[tid] = el * br;
        sL[tid] = lpv;
        sA[tid] = (t > 0) ? g_alpha[(size_t)(b * TT + t - 1) * HH + tid] : 0.0f;
    }
    __syncthreads();

    float e = (tid < HH) ? sG[tid] : 0.0f;
    float Z = blockSum256(e, red);
    float E = blockSum256(e * ((tid < HH) ? sL[tid] : 0.0f), red);
    float total = 0.0f;
    if (t < len) total += E / Z;
    if (t == 0) {
        float P = blockSum256(e * ((tid < HH) ? g_lp[tid] : 0.0f), red);
        total += P / Z;
    }

    if (do_xi) {
        float z = 0.0f, w = 0.0f;
        for (int idx = tid; idx < HH * HH; idx += 256) {
            int i = idx / HH, j = idx - i * HH;
            float val = tp[idx] * sA[i] * sU[j];
            z += val;
            w = fmaf(val, lt[idx], w);
        }
        float Z2 = blockSum256(z, red);
        float W2 = blockSum256(w, red);
        total += W2 / Z2;
    }
    if (tid == 0) g_partial[bt] = total;
}

// ---------------- kernel 5: deterministic final reduction ----------------
__global__ void __launch_bounds__(256) reduce_kernel(float* __restrict__ out) {
    __shared__ float red[256];
    int tid = threadIdx.x;
    float s = 0.0f;
    for (int i = tid; i < MTOT; i += 256) s += g_partial[i];
    red[tid] = s;
    __syncthreads();
    for (int off = 128; off > 0; off >>= 1) {
        if (tid < off) red[tid] += red[tid + off];
        __syncthreads();
    }
    if (tid == 0) out[0] = red[0] * (1.0f / (float)BB);
}

// ---------------- launch ----------------
extern "C" void kernel_launch(void* const* d_in, const int* in_sizes, int n_in,
                              void* d_out, int out_size) {
    const float* emb  = (const float*)d_in[0];
    const float* obs  = (const float*)d_in[1];
    const float* sp   = (const float*)d_in[2];
    const float* ut   = (const float*)d_in[3];
    const float* ue   = (const float*)d_in[4];
    const float* Wm   = (const float*)d_in[5];
    const float* bias = (const float*)d_in[6];
    const int*   seq  = (const int*)d_in[7];
    float* out = (float*)d_out;

    cudaFuncSetAttribute(mma_fused_kernel, cudaFuncAttributeMaxDynamicSharedMemorySize, GEMM_SMEM);

    prep_kernel<<<1, 192>>>(sp, ut, ue);
    {
        const int nA = MTOT * DD / 4, nW = NN * DD / 4;
        convert_kernel<<<(nA + nW + 255) / 256, 256>>>(emb, Wm);
    }

    dim3 ggrid(NN / 192, MTOT / 128);
    mma_fused_kernel<<<ggrid, 512, GEMM_SMEM>>>(bias, obs);
    combine_kernel<<<(MTOT * HH + 255) / 256, 256>>>();

    scan_kernel<<<32, 64>>>();
    final_kernel<<<MTOT, 256>>>(seq);
    reduce_kernel<<<1, 256>>>(out);
}

// round 6
// speedup vs baseline: 4.3040x; 1.0544x over previous
#include <cuda_runtime.h>
#include <cuda_bf16.h>
#include <math.h>
#include <stdint.h>

#define TT 512
#define BB 16
#define HH 48
#define SS 4
#define OO 48
#define DD 768
#define NN 9216      /* S*H*O */
#define MTOT 8192    /* B*T */
#define NGROUP 192   /* S*H */

// ---------------- device scratch ----------------
__device__ __nv_bfloat16 g_emb16[MTOT * DD];
__device__ __nv_bfloat16 g_w16[NN * DD];
__device__ float g_val[MTOT * NGROUP];
__device__ float g_lep[MTOT * HH];
__device__ float g_elep[MTOT * HH];
__device__ float g_alpha[MTOT * HH];   // arbitrary per-t scale
__device__ float g_beta[MTOT * HH];    // arbitrary per-t scale
__device__ float g_partial[MTOT];
__device__ float g_lp[HH];
__device__ float g_log_trans[HH * HH];
__device__ float g_trans_prob[HH * HH];
__device__ float g_emiss_prob[SS * HH * OO];

// ---------------- helpers ----------------
__device__ __forceinline__ uint32_t smem_u32(const void* p) {
    uint32_t a;
    asm("{ .reg .u64 t; cvta.to.shared.u64 t, %1; cvt.u32.u64 %0, t; }" : "=r"(a) : "l"(p));
    return a;
}

__device__ __forceinline__ float fexp(float x) {
    if (x < -87.0f) return 0.0f;
    float t = x * 1.4426950408889634f;
    float n = rintf(t);
    float f = t - n;
    float p = 1.5403530393381609e-4f;
    p = fmaf(p, f, 1.3333558146428443e-3f);
    p = fmaf(p, f, 9.6181291076284772e-3f);
    p = fmaf(p, f, 5.5504108664821580e-2f);
    p = fmaf(p, f, 2.4022650695910072e-1f);
    p = fmaf(p, f, 6.9314718055994531e-1f);
    p = fmaf(p, f, 1.0f);
    int e = (int)n;
    if (e < -126) return 0.0f;
    if (e > 126) e = 126;
    return p * __int_as_float((e + 127) << 23);
}

__device__ __forceinline__ float blockSum256(float v, float* red) {
    int tid = threadIdx.x;
#pragma unroll
    for (int o = 16; o > 0; o >>= 1) v += __shfl_down_sync(0xffffffffu, v, o);
    __syncthreads();
    if ((tid & 31) == 0) red[tid >> 5] = v;
    __syncthreads();
    if (tid < 32) {
        float r = (tid < 8) ? red[tid] : 0.0f;
#pragma unroll
        for (int o = 4; o > 0; o >>= 1) r += __shfl_down_sync(0xffffffffu, r, o);
        if (tid == 0) red[0] = r;
    }
    __syncthreads();
    return red[0];
}

// ---------------- kernel 0: small preprocessing ----------------
__global__ void prep_kernel(const float* __restrict__ sp,
                            const float* __restrict__ ut,
                            const float* __restrict__ ue) {
    int tid = threadIdx.x;
    if (tid < HH) {
        const float* row = ut + tid * HH;
        float m = row[0];
#pragma unroll
        for (int j = 1; j < HH; j++) m = fmaxf(m, row[j]);
        float s = 0.0f;
#pragma unroll
        for (int j = 0; j < HH; j++) s += fexp(row[j] - m);
        float ls = logf(s) + m;
#pragma unroll
        for (int j = 0; j < HH; j++) {
            float v = row[j] - ls;
            g_log_trans[tid * HH + j] = v;
            g_trans_prob[tid * HH + j] = fexp(v);
        }
    }
    if (tid < SS * HH) {
        const float* row = ue + tid * OO;
        float m = row[0];
#pragma unroll
        for (int j = 1; j < OO; j++) m = fmaxf(m, row[j]);
        float s = 0.0f;
#pragma unroll
        for (int j = 0; j < OO; j++) s += fexp(row[j] - m);
        float inv = 1.0f / s;
#pragma unroll
        for (int j = 0; j < OO; j++) g_emiss_prob[tid * OO + j] = fexp(row[j] - m) * inv;
    }
    if (tid == 0) {
        float m = sp[0];
        for (int j = 1; j < HH; j++) m = fmaxf(m, sp[j]);
        float s = 0.0f;
        for (int j = 0; j < HH; j++) s += fexp(sp[j] - m);
        float ls = logf(s) + m;
        for (int j = 0; j < HH; j++) g_lp[j] = sp[j] - ls;
    }
}

// ---------------- kernel 0b: fp32 -> bf16 conversion ----------------
__global__ void __launch_bounds__(256) convert_kernel(const float* __restrict__ emb,
                                                      const float* __restrict__ Wm) {
    const int nA = MTOT * DD / 4;
    const int nW = NN * DD / 4;
    int i = blockIdx.x * 256 + threadIdx.x;
    if (i < nA) {
        float4 v = ((const float4*)emb)[i];
        __nv_bfloat162 lo = __floats2bfloat162_rn(v.x, v.y);
        __nv_bfloat162 hi = __floats2bfloat162_rn(v.z, v.w);
        ((__nv_bfloat162*)g_emb16)[i * 2] = lo;
        ((__nv_bfloat162*)g_emb16)[i * 2 + 1] = hi;
    } else if (i < nA + nW) {
        int j = i - nA;
        float4 v = ((const float4*)Wm)[j];
        __nv_bfloat162 lo = __floats2bfloat162_rn(v.x, v.y);
        __nv_bfloat162 hi = __floats2bfloat162_rn(v.z, v.w);
        ((__nv_bfloat162*)g_w16)[j * 2] = lo;
        ((__nv_bfloat162*)g_w16)[j * 2 + 1] = hi;
    }
}

// dummy launch to position the ncu capture window on mma_fused_kernel
__global__ void dummy_kernel() {}

// ---------------- kernel 1: fused bf16 GEMM (128x96, 256 thr, 4-stage, frag pipeline) ----------------
#define STAGE_BYTES 28672            /* A 16384 + B 12288 */
#define GEMM_SMEM (4 * STAGE_BYTES)  /* 114688 -> 2 CTAs/SM */
__device__ __forceinline__ void cp_async16(uint32_t dst, const void* src) {
    asm volatile("cp.async.cg.shared.global [%0], [%1], 16;" ::
                 "r"(dst), "l"(__cvta_generic_to_global(src)));
}

__global__ void __launch_bounds__(256, 2) mma_fused_kernel(const float* __restrict__ bias,
                                                           const float* __restrict__ obs) {
    extern __shared__ char smem[];
    float* smf = (float*)smem;
    uint32_t sbase = smem_u32(smem);
    const int tid = threadIdx.x;
    const int wid = tid >> 5, lane = tid & 31;
    const int bn = blockIdx.x * 96;           // N base (2 groups)
    const int bm = blockIdx.y * 128;          // M base
    const int wm = (wid >> 1) * 32;           // warp M offset (0,32,64,96)
    const int gsel = wid & 1;                 // warp group select (0/1)
    const int wn = gsel * 48;

    const int sub = lane >> 3, l8 = lane & 7;
    const int a_row_in = (sub & 1) * 8 + l8;
    const int a_kb = (sub >> 1) * 16;
    const int b_row_in = (sub >> 1) * 8 + l8;
    const int b_kb = (sub & 1) * 16;

    uint32_t a_base[2], b_base[3];
    int a_xor[2], b_xor[3];
#pragma unroll
    for (int mi = 0; mi < 2; mi++) {
        int r = wm + mi * 16 + a_row_in;
        a_base[mi] = (uint32_t)(r * 128);
        a_xor[mi] = (r & 7) << 4;
    }
#pragma unroll
    for (int pi = 0; pi < 3; pi++) {
        int r = wn + pi * 16 + b_row_in;
        b_base[pi] = (uint32_t)(r * 128);
        b_xor[pi] = (r & 7) << 4;
    }

    float c[2][6][4];
#pragma unroll
    for (int mi = 0; mi < 2; mi++)
#pragma unroll
        for (int ni = 0; ni < 6; ni++)
#pragma unroll
            for (int q = 0; q < 4; q++) c[mi][ni][q] = 0.0f;

    auto load_tiles = [&](int kb, int stage) {
        uint32_t adst = sbase + (uint32_t)(stage * STAGE_BYTES);
        uint32_t bdst = adst + 16384u;
#pragma unroll
        for (int p = 0; p < 4; p++) {
            int idx = tid + p * 256;
            int r = idx >> 3, cc = idx & 7;
            uint32_t off = (uint32_t)(r * 128 + cc * 16);
            off ^= (uint32_t)((r & 7) << 4);
            cp_async16(adst + off, g_emb16 + (size_t)(bm + r) * DD + kb * 64 + cc * 8);
        }
#pragma unroll
        for (int p = 0; p < 3; p++) {
            int idx = tid + p * 256;
            int r = idx >> 3, cc = idx & 7;
            uint32_t off = (uint32_t)(r * 128 + cc * 16);
            off ^= (uint32_t)((r & 7) << 4);
            cp_async16(bdst + off, g_w16 + (size_t)(bn + r) * DD + kb * 64 + cc * 8);
        }
        asm volatile("cp.async.commit_group;" ::: "memory");
    };

    load_tiles(0, 0);
    load_tiles(1, 1);
    load_tiles(2, 2);

    uint32_t fa[2][2][4];   // [pipe][mi][reg]
    uint32_t fb[2][6][2];   // [pipe][ni][reg]

    for (int kb = 0; kb < 12; kb++) {
        if (kb <= 9)       asm volatile("cp.async.wait_group 2;" ::: "memory");
        else if (kb == 10) asm volatile("cp.async.wait_group 1;" ::: "memory");
        else               asm volatile("cp.async.wait_group 0;" ::: "memory");
        __syncthreads();
        if (kb + 3 < 12) load_tiles(kb + 3, (kb + 3) & 3);

        uint32_t abuf = sbase + (uint32_t)((kb & 3) * STAGE_BYTES);
        uint32_t bbuf = abuf + 16384u;

        auto load_frags = [&](int ks, int pipe) {
#pragma unroll
            for (int mi = 0; mi < 2; mi++) {
                uint32_t addr = abuf + a_base[mi] + (uint32_t)((ks * 32 + a_kb) ^ a_xor[mi]);
                asm volatile("ldmatrix.sync.aligned.m8n8.x4.shared.b16 {%0,%1,%2,%3}, [%4];"
                             : "=r"(fa[pipe][mi][0]), "=r"(fa[pipe][mi][1]),
                               "=r"(fa[pipe][mi][2]), "=r"(fa[pipe][mi][3])
                             : "r"(addr));
            }
#pragma unroll
            for (int pi = 0; pi < 3; pi++) {
                uint32_t addr = bbuf + b_base[pi] + (uint32_t)((ks * 32 + b_kb) ^ b_xor[pi]);
                uint32_t r0, r1, r2, r3;
                asm volatile("ldmatrix.sync.aligned.m8n8.x4.shared.b16 {%0,%1,%2,%3}, [%4];"
                             : "=r"(r0), "=r"(r1), "=r"(r2), "=r"(r3) : "r"(addr));
                fb[pipe][pi * 2][0] = r0; fb[pipe][pi * 2][1] = r1;
                fb[pipe][pi * 2 + 1][0] = r2; fb[pipe][pi * 2 + 1][1] = r3;
            }
        };

        load_frags(0, 0);
#pragma unroll
        for (int ks = 0; ks < 4; ks++) {
            int cur = ks & 1;
            if (ks < 3) load_frags(ks + 1, cur ^ 1);
#pragma unroll
            for (int mi = 0; mi < 2; mi++)
#pragma unroll
                for (int ni = 0; ni < 6; ni++) {
                    asm volatile(
                        "mma.sync.aligned.m16n8k16.row.col.f32.bf16.bf16.f32 "
                        "{%0,%1,%2,%3}, {%4,%5,%6,%7}, {%8,%9}, {%0,%1,%2,%3};"
                        : "+f"(c[mi][ni][0]), "+f"(c[mi][ni][1]),
                          "+f"(c[mi][ni][2]), "+f"(c[mi][ni][3])
                        : "r"(fa[cur][mi][0]), "r"(fa[cur][mi][1]),
                          "r"(fa[cur][mi][2]), "r"(fa[cur][mi][3]),
                          "r"(fb[cur][ni][0]), "r"(fb[cur][ni][1]));
                }
        }
    }

    // ---------------- fused epilogue ----------------
    const int g0 = blockIdx.x * 2;
    const int s_src = g0 / HH;
    const int EPOFF = 6400;
    __syncthreads();
    for (int i = tid; i < 128 * 24; i += 256) {
        int r = i / 24, c2 = i - r * 24;
        float2 v = *(const float2*)&obs[((size_t)(bm + r) * SS + s_src) * OO + c2 * 2];
        *(float2*)&smf[r * 50 + c2 * 2] = v;
    }
    if (tid < 96) smf[EPOFF + tid] = g_emiss_prob[g0 * 48 + tid];
    __syncthreads();

    const int trow = lane >> 2;
    const int tcol = (lane & 3) * 2;
    const int ggl = g0 + gsel;

    float bx[6], by[6];
#pragma unroll
    for (int ni = 0; ni < 6; ni++) {
        float2 bv = *(const float2*)&bias[bn + wn + ni * 8 + tcol];
        bx[ni] = bv.x; by[ni] = bv.y;
    }
    float epx[6], epy[6];
#pragma unroll
    for (int ni = 0; ni < 6; ni++) {
        epx[ni] = smf[EPOFF + gsel * 48 + ni * 8 + tcol];
        epy[ni] = smf[EPOFF + gsel * 48 + ni * 8 + tcol + 1];
    }

#pragma unroll
    for (int mi = 0; mi < 2; mi++) {
#pragma unroll
        for (int half = 0; half < 2; half++) {
            int rt = wm + mi * 16 + half * 8 + trow;
            float vx[6], vy[6];
            float mx = -3.0e38f;
#pragma unroll
            for (int ni = 0; ni < 6; ni++) {
                vx[ni] = c[mi][ni][half * 2] + bx[ni];
                vy[ni] = c[mi][ni][half * 2 + 1] + by[ni];
                mx = fmaxf(mx, fmaxf(vx[ni], vy[ni]));
            }
            mx = fmaxf(mx, __shfl_xor_sync(0xffffffffu, mx, 1));
            mx = fmaxf(mx, __shfl_xor_sync(0xffffffffu, mx, 2));
            float den = 0.0f, dot = 0.0f, eo = 0.0f;
            const float* obr = &smf[rt * 50];
#pragma unroll
            for (int ni = 0; ni < 6; ni++) {
                float obx = obr[ni * 8 + tcol];
                float oby = obr[ni * 8 + tcol + 1];
                float ex = fexp(vx[ni] - mx);
                float ey = fexp(vy[ni] - mx);
                den += ex + ey;
                dot = fmaf(ex, obx, dot);
                dot = fmaf(ey, oby, dot);
                eo = fmaf(epx[ni], obx, eo);
                eo = fmaf(epy[ni], oby, eo);
            }
#pragma unroll
            for (int m = 1; m <= 2; m <<= 1) {
                den += __shfl_xor_sync(0xffffffffu, den, m);
                dot += __shfl_xor_sync(0xffffffffu, dot, m);
                eo  += __shfl_xor_sync(0xffffffffu, eo, m);
            }
            if ((lane & 3) == 0) {
                float val = 0.5f * eo + 0.5f * (dot / den);
                g_val[(size_t)(bm + rt) * NGROUP + ggl] = val;
            }
        }
    }
}

// ---------------- kernel 1b: combine 4 sources -> elep/lep ----------------
__global__ void __launch_bounds__(256) combine_kernel() {
    int idx = blockIdx.x * 256 + threadIdx.x;
    if (idx >= MTOT * HH) return;
    int bt = idx / HH, h = idx - bt * HH;
    const float* v = g_val + (size_t)bt * NGROUP + h;
    float p = v[0] * v[48] * v[96] * v[144];
    g_elep[idx] = p;
    g_lep[idx] = logf(p);
}

// ---------------- kernel 3: scans, prob space, sparse normalization ----------------
__global__ void __launch_bounds__(64) scan_kernel() {
    __shared__ float tp[HH * HH];
    __shared__ float pb[2][HH];
    __shared__ float ubuf[HH];
    __shared__ float ssum;
    int tid = threadIdx.x;
    int b = blockIdx.x & 15;
    bool fwd = blockIdx.x < 16;

    if (fwd) {
        for (int i = tid; i < HH * HH; i += 64) tp[i] = g_trans_prob[i];
        if (tid < HH) {
            float a = fexp(g_lp[tid]) * g_elep[(size_t)(b * TT) * HH + tid];
            pb[0][tid] = a;
            g_alpha[(size_t)(b * TT) * HH + tid] = a;
        }
        __syncthreads();
        float el_next = (tid < HH) ? g_elep[(size_t)(b * TT + 1) * HH + tid] : 0.0f;
        for (int t = 1; t < TT; t++) {
            int cur = t & 1, prev = cur ^ 1;
            float el = el_next;
            if (t + 1 < TT && tid < HH)
                el_next = g_elep[(size_t)(b * TT + t + 1) * HH + tid];
            if (tid < HH) {
                float v0 = 0, v1 = 0, v2 = 0, v3 = 0;
#pragma unroll
                for (int i = 0; i < HH; i += 4) {
                    v0 = fmaf(pb[prev][i + 0], tp[(i + 0) * HH + tid], v0);
                    v1 = fmaf(pb[prev][i + 1], tp[(i + 1) * HH + tid], v1);
                    v2 = fmaf(pb[prev][i + 2], tp[(i + 2) * HH + tid], v2);
                    v3 = fmaf(pb[prev][i + 3], tp[(i + 3) * HH + tid], v3);
                }
                float a = (v0 + v1 + v2 + v3) * el;
                pb[cur][tid] = a;
                g_alpha[(size_t)(b * TT + t) * HH + tid] = a;
            }
            if ((t & 1) == 0) {   // renormalize every 2 steps (underflow guard only)
                __syncthreads();
                if (tid < 32) {
                    float r = pb[cur][tid] + ((tid < 16) ? pb[cur][tid + 32] : 0.0f);
#pragma unroll
                    for (int o = 16; o > 0; o >>= 1) r += __shfl_down_sync(0xffffffffu, r, o);
                    if (tid == 0) ssum = r;
                }
                __syncthreads();
                if (tid < HH) pb[cur][tid] *= (1.0f / ssum);
            }
            __syncthreads();
        }
    } else {
        for (int idx = tid; idx < HH * HH; idx += 64) {
            int i = idx / HH, j = idx - i * HH;
            tp[j * HH + i] = g_trans_prob[idx];
        }
        if (tid < HH) {
            pb[(TT - 1) & 1][tid] = 1.0f;
            g_beta[(size_t)(b * TT + TT - 1) * HH + tid] = 1.0f;
        }
        __syncthreads();
        float el_next = (tid < HH) ? g_elep[(size_t)(b * TT + TT - 2) * HH + tid] : 0.0f;
        for (int t = TT - 2; t >= 0; t--) {
            int cur = t & 1, prev = cur ^ 1;
            float el = el_next;
            if (t - 1 >= 0 && tid < HH)
                el_next = g_elep[(size_t)(b * TT + t - 1) * HH + tid];
            if (tid < HH) ubuf[tid] = el * pb[prev][tid];
            __syncthreads();
            if (tid < HH) {
                float v0 = 0, v1 = 0, v2 = 0, v3 = 0;
#pragma unroll
                for (int j = 0; j < HH; j += 4) {
                    v0 = fmaf(tp[(j + 0) * HH + tid], ubuf[j + 0], v0);
                    v1 = fmaf(tp[(j + 1) * HH + tid], ubuf[j + 1], v1);
                    v2 = fmaf(tp[(j + 2) * HH + tid], ubuf[j + 2], v2);
                    v3 = fmaf(tp[(j + 3) * HH + tid], ubuf[j + 3], v3);
                }
                float bb = v0 + v1 + v2 + v3;
                pb[cur][tid] = bb;
                g_beta[(size_t)(b * TT + t) * HH + tid] = bb;
            }
            if ((t & 1) == 0) {
                __syncthreads();
                if (tid < 32) {
                    float r = pb[cur][tid] + ((tid < 16) ? pb[cur][tid + 32] : 0.0f);
#pragma unroll
                    for (int o = 16; o > 0; o >>= 1) r += __shfl_down_sync(0xffffffffu, r, o);
                    if (tid == 0) ssum = r;
                }
                __syncthreads();
                if (tid < HH) pb[cur][tid] *= (1.0f / ssum);
            }
            __syncthreads();
        }
    }
}

// ---------------- kernel 4: per-(b,t) gamma / prior / xi terms (prob space) ----------------
__global__ void __launch_bounds__(256) final_kernel(const int* __restrict__ seq) {
    __shared__ float lt[HH * HH];
    __shared__ float tp[HH * HH];
    __shared__ float sA[HH], sU[HH], sG[HH], sL[HH];
    __shared__ float red[32];
    int tid = threadIdx.x;
    int bt = blockIdx.x;
    int b = bt >> 9;
    int t = bt & (TT - 1);
    int len = seq[b];

    if (t >= len) {   // contributes nothing (t>=len kills both emis and xi; t==0 < len always)
        if (tid == 0) g_partial[bt] = 0.0f;
        return;
    }
    bool do_xi = (t >= 1);

    for (int i = tid; i < HH * HH; i += 256) {
        lt[i] = g_log_trans[i];
        tp[i] = g_trans_prob[i];
    }
    if (tid < HH) {
        int tb = (t + TT - len) & (TT - 1);
        float br = g_beta[(size_t)(b * TT + tb) * HH + tid];
        float at = g_alpha[(size_t)(b * TT + t) * HH + tid];
        float lpv = g_lep[(size_t)(b * TT + t) * HH + tid];
        float el = g_elep[(size_t)(b * TT + t) * HH + tid];
        sG[tid] = at * br;
        sU[tid] = el * br;
        sL[tid] = lpv;
        sA[tid] = (t > 0) ? g_alpha[(size_t)(b * TT + t - 1) * HH + tid] : 0.0f;
    }
    __syncthreads();

    float e = (tid < HH) ? sG[tid] : 0.0f;
    float Z = blockSum256(e, red);
    float E = blockSum256(e * ((tid < HH) ? sL[tid] : 0.0f), red);
    float total = E / Z;
    if (t == 0) {
        float P = blockSum256(e * ((tid < HH) ? g_lp[tid] : 0.0f), red);
        total += P / Z;
    }

    if (do_xi) {
        float z = 0.0f, w = 0.0f;
        for (int idx = tid; idx < HH * HH; idx += 256) {
            int i = idx / HH, j = idx - i * HH;
            float val = tp[idx] * sA[i] * sU[j];
            z += val;
            w = fmaf(val, lt[idx], w);
        }
        float Z2 = blockSum256(z, red);
        float W2 = blockSum256(w, red);
        total += W2 / Z2;
    }
    if (tid == 0) g_partial[bt] = total;
}

// ---------------- kernel 5: deterministic final reduction ----------------
__global__ void __launch_bounds__(256) reduce_kernel(float* __restrict__ out) {
    __shared__ float red[256];
    int tid = threadIdx.x;
    float s = 0.0f;
    for (int i = tid; i < MTOT; i += 256) s += g_partial[i];
    red[tid] = s;
    __syncthreads();
    for (int off = 128; off > 0; off >>= 1) {
        if (tid < off) red[tid] += red[tid + off];
        __syncthreads();
    }
    if (tid == 0) out[0] = red[0] * (1.0f / (float)BB);
}

// ---------------- launch ----------------
extern "C" void kernel_launch(void* const* d_in, const int* in_sizes, int n_in,
                              void* d_out, int out_size) {
    const float* emb  = (const float*)d_in[0];
    const float* obs  = (const float*)d_in[1];
    const float* sp   = (const float*)d_in[2];
    const float* ut   = (const float*)d_in[3];
    const float* ue   = (const float*)d_in[4];
    const float* Wm   = (const float*)d_in[5];
    const float* bias = (const float*)d_in[6];
    const int*   seq  = (const int*)d_in[7];
    float* out = (float*)d_out;

    cudaFuncSetAttribute(mma_fused_kernel, cudaFuncAttributeMaxDynamicSharedMemorySize, GEMM_SMEM);

    prep_kernel<<<1, 192>>>(sp, ut, ue);                       // launch 1
    {
        const int nA = MTOT * DD / 4, nW = NN * DD / 4;
        convert_kernel<<<(nA + nW + 255) / 256, 256>>>(emb, Wm);  // launch 2
    }
    dummy_kernel<<<1, 32>>>();                                  // launch 3 (ncu positioning)

    dim3 ggrid(NN / 96, MTOT / 128);
    mma_fused_kernel<<<ggrid, 256, GEMM_SMEM>>>(bias, obs);     // launch 4 <- ncu window
    combine_kernel<<<(MTOT * HH + 255) / 256, 256>>>();

    scan_kernel<<<32, 64>>>();
    final_kernel<<<MTOT, 256>>>(seq);
    reduce_kernel<<<1, 256>>>(out);
}

// round 7
// speedup vs baseline: 5.2916x; 1.2295x over previous
#include <cuda_runtime.h>
#include <cuda_bf16.h>
#include <math.h>
#include <stdint.h>

#define TT 512
#define BB 16
#define HH 48
#define SS 4
#define OO 48
#define DD 768
#define NN 9216      /* S*H*O */
#define MTOT 8192    /* B*T */
#define NGROUP 192   /* S*H */

// ---------------- device scratch ----------------
__device__ __nv_bfloat16 g_emb16[MTOT * DD];
__device__ __nv_bfloat16 g_w16[NN * DD];
__device__ float g_val[MTOT * NGROUP];
__device__ float g_lep[MTOT * HH];
__device__ float g_elep[MTOT * HH];
__device__ float g_alpha[MTOT * HH];   // arbitrary per-t scale
__device__ float g_beta[MTOT * HH];    // arbitrary per-t scale
__device__ float g_partial[MTOT];
__device__ float g_lp[HH];
__device__ float g_log_trans[HH * HH];
__device__ float g_trans_prob[HH * HH];
__device__ float g_emiss_prob[SS * HH * OO];

// ---------------- helpers ----------------
__device__ __forceinline__ uint32_t smem_u32(const void* p) {
    uint32_t a;
    asm("{ .reg .u64 t; cvta.to.shared.u64 t, %1; cvt.u32.u64 %0, t; }" : "=r"(a) : "l"(p));
    return a;
}

__device__ __forceinline__ float fexp(float x) {
    if (x < -87.0f) return 0.0f;
    float t = x * 1.4426950408889634f;
    float n = rintf(t);
    float f = t - n;
    float p = 1.5403530393381609e-4f;
    p = fmaf(p, f, 1.3333558146428443e-3f);
    p = fmaf(p, f, 9.6181291076284772e-3f);
    p = fmaf(p, f, 5.5504108664821580e-2f);
    p = fmaf(p, f, 2.4022650695910072e-1f);
    p = fmaf(p, f, 6.9314718055994531e-1f);
    p = fmaf(p, f, 1.0f);
    int e = (int)n;
    if (e < -126) return 0.0f;
    if (e > 126) e = 126;
    return p * __int_as_float((e + 127) << 23);
}

__device__ __forceinline__ float blockSum256(float v, float* red) {
    int tid = threadIdx.x;
#pragma unroll
    for (int o = 16; o > 0; o >>= 1) v += __shfl_down_sync(0xffffffffu, v, o);
    __syncthreads();
    if ((tid & 31) == 0) red[tid >> 5] = v;
    __syncthreads();
    if (tid < 32) {
        float r = (tid < 8) ? red[tid] : 0.0f;
#pragma unroll
        for (int o = 4; o > 0; o >>= 1) r += __shfl_down_sync(0xffffffffu, r, o);
        if (tid == 0) red[0] = r;
    }
    __syncthreads();
    return red[0];
}

// ---------------- kernel 0: convert + prep merged (single launch) ----------------
#define CONV_BLOCKS 13056   /* (MTOT*DD/4 + NN*DD/4) / 256 exactly */
__global__ void __launch_bounds__(256) init_kernel(const float* __restrict__ emb,
                                                   const float* __restrict__ Wm,
                                                   const float* __restrict__ sp,
                                                   const float* __restrict__ ut,
                                                   const float* __restrict__ ue) {
    const int nA = MTOT * DD / 4;
    const int nW = NN * DD / 4;
    int blk = blockIdx.x;
    int tid = threadIdx.x;
    if (blk < CONV_BLOCKS) {
        int i = blk * 256 + tid;
        if (i < nA) {
            float4 v = ((const float4*)emb)[i];
            __nv_bfloat162 lo = __floats2bfloat162_rn(v.x, v.y);
            __nv_bfloat162 hi = __floats2bfloat162_rn(v.z, v.w);
            ((__nv_bfloat162*)g_emb16)[i * 2] = lo;
            ((__nv_bfloat162*)g_emb16)[i * 2 + 1] = hi;
        } else if (i < nA + nW) {
            int j = i - nA;
            float4 v = ((const float4*)Wm)[j];
            __nv_bfloat162 lo = __floats2bfloat162_rn(v.x, v.y);
            __nv_bfloat162 hi = __floats2bfloat162_rn(v.z, v.w);
            ((__nv_bfloat162*)g_w16)[j * 2] = lo;
            ((__nv_bfloat162*)g_w16)[j * 2 + 1] = hi;
        }
        return;
    }
    // ---- prep work (last block) ----
    if (tid < HH) {
        const float* row = ut + tid * HH;
        float m = row[0];
#pragma unroll
        for (int j = 1; j < HH; j++) m = fmaxf(m, row[j]);
        float s = 0.0f;
#pragma unroll
        for (int j = 0; j < HH; j++) s += fexp(row[j] - m);
        float ls = logf(s) + m;
#pragma unroll
        for (int j = 0; j < HH; j++) {
            float v = row[j] - ls;
            g_log_trans[tid * HH + j] = v;
            g_trans_prob[tid * HH + j] = fexp(v);
        }
    }
    if (tid < SS * HH) {
        const float* row = ue + tid * OO;
        float m = row[0];
#pragma unroll
        for (int j = 1; j < OO; j++) m = fmaxf(m, row[j]);
        float s = 0.0f;
#pragma unroll
        for (int j = 0; j < OO; j++) s += fexp(row[j] - m);
        float inv = 1.0f / s;
#pragma unroll
        for (int j = 0; j < OO; j++) g_emiss_prob[tid * OO + j] = fexp(row[j] - m) * inv;
    }
    if (tid == 0) {
        float m = sp[0];
        for (int j = 1; j < HH; j++) m = fmaxf(m, sp[j]);
        float s = 0.0f;
        for (int j = 0; j < HH; j++) s += fexp(sp[j] - m);
        float ls = logf(s) + m;
        for (int j = 0; j < HH; j++) g_lp[j] = sp[j] - ls;
    }
}

// ---------------- kernel 1: fused bf16 GEMM (128x96, 256 thr, 4-stage, frag pipeline) ----------------
#define STAGE_BYTES 28672            /* A 16384 + B 12288 */
#define GEMM_SMEM (4 * STAGE_BYTES)  /* 114688 -> 2 CTAs/SM */
__device__ __forceinline__ void cp_async16(uint32_t dst, const void* src) {
    asm volatile("cp.async.cg.shared.global [%0], [%1], 16;" ::
                 "r"(dst), "l"(__cvta_generic_to_global(src)));
}

__global__ void __launch_bounds__(256, 2) mma_fused_kernel(const float* __restrict__ bias,
                                                           const float* __restrict__ obs) {
    extern __shared__ char smem[];
    float* smf = (float*)smem;
    uint32_t sbase = smem_u32(smem);
    const int tid = threadIdx.x;
    const int wid = tid >> 5, lane = tid & 31;
    const int bn = blockIdx.x * 96;
    const int bm = blockIdx.y * 128;
    const int wm = (wid >> 1) * 32;
    const int gsel = wid & 1;
    const int wn = gsel * 48;

    const int sub = lane >> 3, l8 = lane & 7;
    const int a_row_in = (sub & 1) * 8 + l8;
    const int a_kb = (sub >> 1) * 16;
    const int b_row_in = (sub >> 1) * 8 + l8;
    const int b_kb = (sub & 1) * 16;

    uint32_t a_base[2], b_base[3];
    int a_xor[2], b_xor[3];
#pragma unroll
    for (int mi = 0; mi < 2; mi++) {
        int r = wm + mi * 16 + a_row_in;
        a_base[mi] = (uint32_t)(r * 128);
        a_xor[mi] = (r & 7) << 4;
    }
#pragma unroll
    for (int pi = 0; pi < 3; pi++) {
        int r = wn + pi * 16 + b_row_in;
        b_base[pi] = (uint32_t)(r * 128);
        b_xor[pi] = (r & 7) << 4;
    }

    float c[2][6][4];
#pragma unroll
    for (int mi = 0; mi < 2; mi++)
#pragma unroll
        for (int ni = 0; ni < 6; ni++)
#pragma unroll
            for (int q = 0; q < 4; q++) c[mi][ni][q] = 0.0f;

    auto load_tiles = [&](int kb, int stage) {
        uint32_t adst = sbase + (uint32_t)(stage * STAGE_BYTES);
        uint32_t bdst = adst + 16384u;
#pragma unroll
        for (int p = 0; p < 4; p++) {
            int idx = tid + p * 256;
            int r = idx >> 3, cc = idx & 7;
            uint32_t off = (uint32_t)(r * 128 + cc * 16);
            off ^= (uint32_t)((r & 7) << 4);
            cp_async16(adst + off, g_emb16 + (size_t)(bm + r) * DD + kb * 64 + cc * 8);
        }
#pragma unroll
        for (int p = 0; p < 3; p++) {
            int idx = tid + p * 256;
            int r = idx >> 3, cc = idx & 7;
            uint32_t off = (uint32_t)(r * 128 + cc * 16);
            off ^= (uint32_t)((r & 7) << 4);
            cp_async16(bdst + off, g_w16 + (size_t)(bn + r) * DD + kb * 64 + cc * 8);
        }
        asm volatile("cp.async.commit_group;" ::: "memory");
    };

    load_tiles(0, 0);
    load_tiles(1, 1);
    load_tiles(2, 2);

    uint32_t fa[2][2][4];
    uint32_t fb[2][6][2];

    for (int kb = 0; kb < 12; kb++) {
        if (kb <= 9)       asm volatile("cp.async.wait_group 2;" ::: "memory");
        else if (kb == 10) asm volatile("cp.async.wait_group 1;" ::: "memory");
        else               asm volatile("cp.async.wait_group 0;" ::: "memory");
        __syncthreads();
        if (kb + 3 < 12) load_tiles(kb + 3, (kb + 3) & 3);

        uint32_t abuf = sbase + (uint32_t)((kb & 3) * STAGE_BYTES);
        uint32_t bbuf = abuf + 16384u;

        auto load_frags = [&](int ks, int pipe) {
#pragma unroll
            for (int mi = 0; mi < 2; mi++) {
                uint32_t addr = abuf + a_base[mi] + (uint32_t)((ks * 32 + a_kb) ^ a_xor[mi]);
                asm volatile("ldmatrix.sync.aligned.m8n8.x4.shared.b16 {%0,%1,%2,%3}, [%4];"
                             : "=r"(fa[pipe][mi][0]), "=r"(fa[pipe][mi][1]),
                               "=r"(fa[pipe][mi][2]), "=r"(fa[pipe][mi][3])
                             : "r"(addr));
            }
#pragma unroll
            for (int pi = 0; pi < 3; pi++) {
                uint32_t addr = bbuf + b_base[pi] + (uint32_t)((ks * 32 + b_kb) ^ b_xor[pi]);
                uint32_t r0, r1, r2, r3;
                asm volatile("ldmatrix.sync.aligned.m8n8.x4.shared.b16 {%0,%1,%2,%3}, [%4];"
                             : "=r"(r0), "=r"(r1), "=r"(r2), "=r"(r3) : "r"(addr));
                fb[pipe][pi * 2][0] = r0; fb[pipe][pi * 2][1] = r1;
                fb[pipe][pi * 2 + 1][0] = r2; fb[pipe][pi * 2 + 1][1] = r3;
            }
        };

        load_frags(0, 0);
#pragma unroll
        for (int ks = 0; ks < 4; ks++) {
            int cur = ks & 1;
            if (ks < 3) load_frags(ks + 1, cur ^ 1);
#pragma unroll
            for (int mi = 0; mi < 2; mi++)
#pragma unroll
                for (int ni = 0; ni < 6; ni++) {
                    asm volatile(
                        "mma.sync.aligned.m16n8k16.row.col.f32.bf16.bf16.f32 "
                        "{%0,%1,%2,%3}, {%4,%5,%6,%7}, {%8,%9}, {%0,%1,%2,%3};"
                        : "+f"(c[mi][ni][0]), "+f"(c[mi][ni][1]),
                          "+f"(c[mi][ni][2]), "+f"(c[mi][ni][3])
                        : "r"(fa[cur][mi][0]), "r"(fa[cur][mi][1]),
                          "r"(fa[cur][mi][2]), "r"(fa[cur][mi][3]),
                          "r"(fb[cur][ni][0]), "r"(fb[cur][ni][1]));
                }
        }
    }

    // ---------------- fused epilogue ----------------
    const int g0 = blockIdx.x * 2;
    const int s_src = g0 / HH;
    const int EPOFF = 6400;
    __syncthreads();
    for (int i = tid; i < 128 * 24; i += 256) {
        int r = i / 24, c2 = i - r * 24;
        float2 v = *(const float2*)&obs[((size_t)(bm + r) * SS + s_src) * OO + c2 * 2];
        *(float2*)&smf[r * 50 + c2 * 2] = v;
    }
    if (tid < 96) smf[EPOFF + tid] = g_emiss_prob[g0 * 48 + tid];
    __syncthreads();

    const int trow = lane >> 2;
    const int tcol = (lane & 3) * 2;
    const int ggl = g0 + gsel;

    float bx[6], by[6];
#pragma unroll
    for (int ni = 0; ni < 6; ni++) {
        float2 bv = *(const float2*)&bias[bn + wn + ni * 8 + tcol];
        bx[ni] = bv.x; by[ni] = bv.y;
    }
    float epx[6], epy[6];
#pragma unroll
    for (int ni = 0; ni < 6; ni++) {
        epx[ni] = smf[EPOFF + gsel * 48 + ni * 8 + tcol];
        epy[ni] = smf[EPOFF + gsel * 48 + ni * 8 + tcol + 1];
    }

#pragma unroll
    for (int mi = 0; mi < 2; mi++) {
#pragma unroll
        for (int half = 0; half < 2; half++) {
            int rt = wm + mi * 16 + half * 8 + trow;
            float vx[6], vy[6];
            float mx = -3.0e38f;
#pragma unroll
            for (int ni = 0; ni < 6; ni++) {
                vx[ni] = c[mi][ni][half * 2] + bx[ni];
                vy[ni] = c[mi][ni][half * 2 + 1] + by[ni];
                mx = fmaxf(mx, fmaxf(vx[ni], vy[ni]));
            }
            mx = fmaxf(mx, __shfl_xor_sync(0xffffffffu, mx, 1));
            mx = fmaxf(mx, __shfl_xor_sync(0xffffffffu, mx, 2));
            float den = 0.0f, dot = 0.0f, eo = 0.0f;
            const float* obr = &smf[rt * 50];
#pragma unroll
            for (int ni = 0; ni < 6; ni++) {
                float obx = obr[ni * 8 + tcol];
                float oby = obr[ni * 8 + tcol + 1];
                float ex = fexp(vx[ni] - mx);
                float ey = fexp(vy[ni] - mx);
                den += ex + ey;
                dot = fmaf(ex, obx, dot);
                dot = fmaf(ey, oby, dot);
                eo = fmaf(epx[ni], obx, eo);
                eo = fmaf(epy[ni], oby, eo);
            }
#pragma unroll
            for (int m = 1; m <= 2; m <<= 1) {
                den += __shfl_xor_sync(0xffffffffu, den, m);
                dot += __shfl_xor_sync(0xffffffffu, dot, m);
                eo  += __shfl_xor_sync(0xffffffffu, eo, m);
            }
            if ((lane & 3) == 0) {
                float val = 0.5f * eo + 0.5f * (dot / den);
                g_val[(size_t)(bm + rt) * NGROUP + ggl] = val;
            }
        }
    }
}

// ---------------- kernel 1b: combine 4 sources -> elep/lep ----------------
__global__ void __launch_bounds__(256) combine_kernel() {
    int idx = blockIdx.x * 256 + threadIdx.x;
    if (idx >= MTOT * HH) return;
    int bt = idx / HH, h = idx - bt * HH;
    const float* v = g_val + (size_t)bt * NGROUP + h;
    float p = v[0] * v[48] * v[96] * v[144];
    g_elep[idx] = p;
    g_lep[idx] = logf(p);
}

// ---------------- kernel 3: barrier-free single-warp scans ----------------
// block = 1 warp. blocks 0..15 forward (per b), 16..31 backward.
// lane l owns state indices {l} and {32+l | l<16}. trans in registers.
__global__ void __launch_bounds__(32) scan_kernel() {
    const unsigned FULL = 0xffffffffu;
    int l = threadIdx.x;
    int b = blockIdx.x & 15;
    bool fwd = blockIdx.x < 16;
    bool two = l < 16;
    const float* E = g_elep + (size_t)(b * TT) * HH;

    float T0[HH], T1[HH];
    if (fwd) {
        // columns: T0[i] = trans[i][l], T1[i] = trans[i][32+l]
#pragma unroll
        for (int i = 0; i < HH; i++) {
            T0[i] = g_trans_prob[i * HH + l];
            T1[i] = two ? g_trans_prob[i * HH + 32 + l] : 0.0f;
        }
        float a0 = fexp(g_lp[l]) * E[l];
        float a1 = two ? fexp(g_lp[32 + l]) * E[32 + l] : 0.0f;
        g_alpha[(size_t)(b * TT) * HH + l] = a0;
        if (two) g_alpha[(size_t)(b * TT) * HH + 32 + l] = a1;
        float eA0 = E[HH + l];
        float eA1 = two ? E[HH + 32 + l] : 0.0f;
        float eB0 = E[2 * HH + l];
        float eB1 = two ? E[2 * HH + 32 + l] : 0.0f;
        for (int t = 1; t < TT; t++) {
            float el0 = eA0, el1 = eA1;
            eA0 = eB0; eA1 = eB1;
            if (t + 2 < TT) {
                eB0 = E[(t + 2) * HH + l];
                eB1 = two ? E[(t + 2) * HH + 32 + l] : 0.0f;
            }
            float p0 = 0, p1 = 0, p2 = 0, p3 = 0;
            float q0 = 0, q1 = 0, q2 = 0, q3 = 0;
#pragma unroll
            for (int i = 0; i < 32; i += 4) {
                float v0 = __shfl_sync(FULL, a0, i);
                float v1 = __shfl_sync(FULL, a0, i + 1);
                float v2 = __shfl_sync(FULL, a0, i + 2);
                float v3 = __shfl_sync(FULL, a0, i + 3);
                p0 = fmaf(v0, T0[i], p0);     q0 = fmaf(v0, T1[i], q0);
                p1 = fmaf(v1, T0[i + 1], p1); q1 = fmaf(v1, T1[i + 1], q1);
                p2 = fmaf(v2, T0[i + 2], p2); q2 = fmaf(v2, T1[i + 2], q2);
                p3 = fmaf(v3, T0[i + 3], p3); q3 = fmaf(v3, T1[i + 3], q3);
            }
#pragma unroll
            for (int i = 0; i < 16; i += 4) {
                float v0 = __shfl_sync(FULL, a1, i);
                float v1 = __shfl_sync(FULL, a1, i + 1);
                float v2 = __shfl_sync(FULL, a1, i + 2);
                float v3 = __shfl_sync(FULL, a1, i + 3);
                p0 = fmaf(v0, T0[32 + i], p0);     q0 = fmaf(v0, T1[32 + i], q0);
                p1 = fmaf(v1, T0[32 + i + 1], p1); q1 = fmaf(v1, T1[32 + i + 1], q1);
                p2 = fmaf(v2, T0[32 + i + 2], p2); q2 = fmaf(v2, T1[32 + i + 2], q2);
                p3 = fmaf(v3, T0[32 + i + 3], p3); q3 = fmaf(v3, T1[32 + i + 3], q3);
            }
            a0 = (p0 + p1 + p2 + p3) * el0;
            a1 = (q0 + q1 + q2 + q3) * el1;   // el1=0 for l>=16 keeps a1=0
            g_alpha[(size_t)(b * TT + t) * HH + l] = a0;
            if (two) g_alpha[(size_t)(b * TT + t) * HH + 32 + l] = a1;
            if ((t & 1) == 0) {               // underflow guard every 2 steps
                float s = a0 + a1;
#pragma unroll
                for (int o = 16; o > 0; o >>= 1) s += __shfl_xor_sync(FULL, s, o);
                float inv = 1.0f / s;
                a0 *= inv; a1 *= inv;
            }
        }
    } else {
        // rows: T0[j] = trans[l][j], T1[j] = trans[32+l][j]
#pragma unroll
        for (int j = 0; j < HH; j++) {
            T0[j] = g_trans_prob[l * HH + j];
            T1[j] = two ? g_trans_prob[(32 + l) * HH + j] : 0.0f;
        }
        float b0 = 1.0f;
        float b1 = two ? 1.0f : 0.0f;
        g_beta[(size_t)(b * TT + TT - 1) * HH + l] = 1.0f;
        if (two) g_beta[(size_t)(b * TT + TT - 1) * HH + 32 + l] = 1.0f;
        float eA0 = E[(TT - 2) * HH + l];
        float eA1 = two ? E[(TT - 2) * HH + 32 + l] : 0.0f;
        float eB0 = E[(TT - 3) * HH + l];
        float eB1 = two ? E[(TT - 3) * HH + 32 + l] : 0.0f;
        for (int t = TT - 2; t >= 0; t--) {
            float el0 = eA0, el1 = eA1;
            eA0 = eB0; eA1 = eB1;
            if (t - 2 >= 0) {
                eB0 = E[(t - 2) * HH + l];
                eB1 = two ? E[(t - 2) * HH + 32 + l] : 0.0f;
            }
            float u0 = el0 * b0;
            float u1 = el1 * b1;   // 0 for l>=16
            float p0 = 0, p1 = 0, p2 = 0, p3 = 0;
            float q0 = 0, q1 = 0, q2 = 0, q3 = 0;
#pragma unroll
            for (int j = 0; j < 32; j += 4) {
                float v0 = __shfl_sync(FULL, u0, j);
                float v1 = __shfl_sync(FULL, u0, j + 1);
                float v2 = __shfl_sync(FULL, u0, j + 2);
                float v3 = __shfl_sync(FULL, u0, j + 3);
                p0 = fmaf(v0, T0[j], p0);     q0 = fmaf(v0, T1[j], q0);
                p1 = fmaf(v1, T0[j + 1], p1); q1 = fmaf(v1, T1[j + 1], q1);
                p2 = fmaf(v2, T0[j + 2], p2); q2 = fmaf(v2, T1[j + 2], q2);
                p3 = fmaf(v3, T0[j + 3], p3); q3 = fmaf(v3, T1[j + 3], q3);
            }
#pragma unroll
            for (int j = 0; j < 16; j += 4) {
                float v0 = __shfl_sync(FULL, u1, j);
                float v1 = __shfl_sync(FULL, u1, j + 1);
                float v2 = __shfl_sync(FULL, u1, j + 2);
                float v3 = __shfl_sync(FULL, u1, j + 3);
                p0 = fmaf(v0, T0[32 + j], p0);     q0 = fmaf(v0, T1[32 + j], q0);
                p1 = fmaf(v1, T0[32 + j + 1], p1); q1 = fmaf(v1, T1[32 + j + 1], q1);
                p2 = fmaf(v2, T0[32 + j + 2], p2); q2 = fmaf(v2, T1[32 + j + 2], q2);
                p3 = fmaf(v3, T0[32 + j + 3], p3); q3 = fmaf(v3, T1[32 + j + 3], q3);
            }
            b0 = p0 + p1 + p2 + p3;
            b1 = q0 + q1 + q2 + q3;   // stays 0 for l>=16 (T1=0)
            g_beta[(size_t)(b * TT + t) * HH + l] = b0;
            if (two) g_beta[(size_t)(b * TT + t) * HH + 32 + l] = b1;
            if ((t & 1) == 0) {
                float s = b0 + b1;
#pragma unroll
                for (int o = 16; o > 0; o >>= 1) s += __shfl_xor_sync(FULL, s, o);
                float inv = 1.0f / s;
                b0 *= inv; b1 *= inv;
            }
        }
    }
}

// ---------------- kernel 4: per-(b,t) gamma / prior / xi terms (prob space) ----------------
__global__ void __launch_bounds__(256) final_kernel(const int* __restrict__ seq) {
    __shared__ float lt[HH * HH];
    __shared__ float tp[HH * HH];
    __shared__ float sA[HH], sU[HH], sG[HH], sL[HH];
    __shared__ float red[32];
    int tid = threadIdx.x;
    int bt = blockIdx.x;
    int b = bt >> 9;
    int t = bt & (TT - 1);
    int len = seq[b];

    if (t >= len) {
        if (tid == 0) g_partial[bt] = 0.0f;
        return;
    }
    bool do_xi = (t >= 1);

    for (int i = tid; i < HH * HH; i += 256) {
        lt[i] = g_log_trans[i];
        tp[i] = g_trans_prob[i];
    }
    if (tid < HH) {
        int tb = (t + TT - len) & (TT - 1);
        float br = g_beta[(size_t)(b * TT + tb) * HH + tid];
        float at = g_alpha[(size_t)(b * TT + t) * HH + tid];
        float lpv = g_lep[(size_t)(b * TT + t) * HH + tid];
        float el = g_elep[(size_t)(b * TT + t) * HH + tid];
        sG[tid] = at * br;
        sU[tid] = el * br;
        sL[tid] = lpv;
        sA[tid] = (t > 0) ? g_alpha[(size_t)(b * TT + t - 1) * HH + tid] : 0.0f;
    }
    __syncthreads();

    float e = (tid < HH) ? sG[tid] : 0.0f;
    float Z = blockSum256(e, red);
    float E = blockSum256(e * ((tid < HH) ? sL[tid] : 0.0f), red);
    float total = E / Z;
    if (t == 0) {
        float P = blockSum256(e * ((tid < HH) ? g_lp[tid] : 0.0f), red);
        total += P / Z;
    }

    if (do_xi) {
        float z = 0.0f, w = 0.0f;
        for (int idx = tid; idx < HH * HH; idx += 256) {
            int i = idx / HH, j = idx - i * HH;
            float val = tp[idx] * sA[i] * sU[j];
            z += val;
            w = fmaf(val, lt[idx], w);
        }
        float Z2 = blockSum256(z, red);
        float W2 = blockSum256(w, red);
        total += W2 / Z2;
    }
    if (tid == 0) g_partial[bt] = total;
}

// ---------------- kernel 5: deterministic final reduction ----------------
__global__ void __launch_bounds__(256) reduce_kernel(float* __restrict__ out) {
    __shared__ float red[256];
    int tid = threadIdx.x;
    float s = 0.0f;
    for (int i = tid; i < MTOT; i += 256) s += g_partial[i];
    red[tid] = s;
    __syncthreads();
    for (int off = 128; off > 0; off >>= 1) {
        if (tid < off) red[tid] += red[tid + off];
        __syncthreads();
    }
    if (tid == 0) out[0] = red[0] * (1.0f / (float)BB);
}

// ---------------- launch ----------------
extern "C" void kernel_launch(void* const* d_in, const int* in_sizes, int n_in,
                              void* d_out, int out_size) {
    const float* emb  = (const float*)d_in[0];
    const float* obs  = (const float*)d_in[1];
    const float* sp   = (const float*)d_in[2];
    const float* ut   = (const float*)d_in[3];
    const float* ue   = (const float*)d_in[4];
    const float* Wm   = (const float*)d_in[5];
    const float* bias = (const float*)d_in[6];
    const int*   seq  = (const int*)d_in[7];
    float* out = (float*)d_out;

    cudaFuncSetAttribute(mma_fused_kernel, cudaFuncAttributeMaxDynamicSharedMemorySize, GEMM_SMEM);

    init_kernel<<<CONV_BLOCKS + 1, 256>>>(emb, Wm, sp, ut, ue);   // launch 1

    dim3 ggrid(NN / 96, MTOT / 128);
    mma_fused_kernel<<<ggrid, 256, GEMM_SMEM>>>(bias, obs);       // launch 2
    combine_kernel<<<(MTOT * HH + 255) / 256, 256>>>();           // launch 3

    scan_kernel<<<32, 32>>>();                                    // launch 4 <- ncu window
    final_kernel<<<MTOT, 256>>>(seq);                             // launch 5
    reduce_kernel<<<1, 256>>>(out);                               // launch 6
}